// round 13
// baseline (speedup 1.0000x reference)
#include <cuda_runtime.h>
#include <cuda_bf16.h>
#include <math.h>
#include <stdint.h>
#include <stddef.h>

#define NTRAJ  256
#define NTP    512
#define LATENT 256
#define INPUT  128
#define NUNITS 256
#define GIN    (LATENT + INPUT)   // 384
#define DEC_OUT 128
#define NSTEP  (NTP - 1)          // 511

#define G       4                 // trajectories per cluster
#define NCLU    (NTRAJ / G)       // 64 clusters
#define NBLK    (NCLU * 2)        // 128 CTAs (2 per cluster, N-split)
#define THREADS 512               // intra-CTA split-K x4 (kq groups)

typedef unsigned long long u64;

union F2U { float2 f; u64 u; };

__device__ __forceinline__ u64 ffma2(u64 a, u64 b, u64 c) {
    u64 d;
    asm("fma.rn.f32x2 %0, %1, %2, %3;" : "=l"(d) : "l"(a), "l"(b), "l"(c));
    return d;
}
__device__ __forceinline__ float lanesum(u64 v) {
    F2U r; r.u = v; return r.f.x + r.f.y;
}
__device__ __forceinline__ float sigmoid_fast(float x) {
    return __fdividef(1.f, 1.f + __expf(-x));
}
__device__ __forceinline__ uint32_t smem_u32(const void* p) {
    uint32_t a;
    asm("{ .reg .u64 t; cvta.to.shared.u64 t, %1; cvt.u32.u64 %0, t; }" : "=r"(a) : "l"(p));
    return a;
}
__device__ __forceinline__ uint32_t ctarank() {
    uint32_t r; asm("mov.u32 %0, %%cluster_ctarank;" : "=r"(r)); return r;
}
__device__ __forceinline__ uint32_t mapa_u32(uint32_t addr, uint32_t rank) {
    uint32_t r;
    asm("mapa.shared::cluster.u32 %0, %1, %2;" : "=r"(r) : "r"(addr), "r"(rank));
    return r;
}
__device__ __forceinline__ void st_peer_f1(uint32_t dst, float v) {
    asm volatile("st.shared::cluster.u32 [%0], %1;" :: "r"(dst), "f"(v) : "memory");
}
#define CLUSTER_SYNC() do { \
    asm volatile("barrier.cluster.arrive.aligned;" ::: "memory"); \
    asm volatile("barrier.cluster.wait.aligned;"   ::: "memory"); \
} while (0)

// ---------------------------------------------------------------------------
// Packed weights: float4 along k: W4[k4][j] = W[4k4..4k4+3][j], as ulonglong2.
// ---------------------------------------------------------------------------
#define SZ_M384 (96 * 256)
#define SZ_M256 (64 * 256)
#define SZ_DEC  (64 * 128)
#define OFF_UG1  0
#define OFF_UGT1 (OFF_UG1  + SZ_M384)
#define OFF_RG1  (OFF_UGT1 + SZ_M384)
#define OFF_NS1  (OFF_RG1  + SZ_M384)
#define OFF_UG2  (OFF_NS1  + SZ_M384)
#define OFF_UGT2 (OFF_UG2  + SZ_M256)
#define OFF_RG2  (OFF_UGT2 + SZ_M256)
#define OFF_NS2  (OFF_RG2  + SZ_M256)
#define OFF_DK1  (OFF_NS2  + SZ_M256)
#define OFF_DEC  (OFF_DK1  + SZ_M256)
#define WP_TOTAL (OFF_DEC  + SZ_DEC)

__device__ ulonglong2 g_wp[WP_TOTAL];

__global__ void pack_kernel(
    const float* ug1, const float* ugt1, const float* rg1, const float* ns1,
    const float* ug2, const float* ugt2, const float* rg2, const float* ns2,
    const float* dk1, const float* decw)
{
    const float* srcs[10] = {ug1, ugt1, rg1, ns1, ug2, ugt2, rg2, ns2, dk1, decw};
    const int offs[11] = {OFF_UG1, OFF_UGT1, OFF_RG1, OFF_NS1, OFF_UG2, OFF_UGT2,
                          OFF_RG2, OFF_NS2, OFF_DK1, OFF_DEC, WP_TOTAL};
    const int Ns[10] = {256,256,256,256,256,256,256,256,256,128};

    int idx = blockIdx.x * blockDim.x + threadIdx.x;
    if (idx >= WP_TOTAL) return;
    int m = 0;
    while (idx >= offs[m + 1]) m++;
    int local = idx - offs[m];
    int N = Ns[m];
    int k4 = local / N, j = local % N;
    const float* S = srcs[m];
    F2U lo, hi;
    lo.f = make_float2(S[(4 * k4 + 0) * N + j], S[(4 * k4 + 1) * N + j]);
    hi.f = make_float2(S[(4 * k4 + 2) * N + j], S[(4 * k4 + 3) * N + j]);
    g_wp[idx] = make_ulonglong2(lo.u, hi.u);
}

// ---------------------------------------------------------------------------
// Partial packed GEMV (quarter-K), shared activation. A/B register buffer.
// ---------------------------------------------------------------------------
template <int K2H, int NG, int N, int CU>
__device__ __forceinline__ void gemv_part(
    float (&res)[NG][G],
    const ulonglong2* const (&Wv)[NG],
    const float* act, int astride, int j)
{
    constexpr int K4 = K2H / 2;
    constexpr int CH = K4 / CU;
    static_assert(CH % 2 == 0, "chunks must be even");

    u64 acc[NG][G];
#pragma unroll
    for (int ng = 0; ng < NG; ng++)
#pragma unroll
        for (int g = 0; g < G; g++) acc[ng][g] = 0ull;

    ulonglong2 wA[NG][CU], wB[NG][CU];

    auto LD = [&](ulonglong2 (&w)[NG][CU], int c) {
#pragma unroll
        for (int ng = 0; ng < NG; ng++)
#pragma unroll
            for (int cu = 0; cu < CU; cu++)
                w[ng][cu] = Wv[ng][(c * CU + cu) * N + j];
    };
    auto CP = [&](ulonglong2 (&w)[NG][CU], int c) {
#pragma unroll
        for (int cu = 0; cu < CU; cu++) {
            int k4 = c * CU + cu;
#pragma unroll
            for (int g = 0; g < G; g++) {
                ulonglong2 av = *(const ulonglong2*)(act + g * astride + 4 * k4);
#pragma unroll
                for (int ng = 0; ng < NG; ng++) {
                    acc[ng][g] = ffma2(av.x, w[ng][cu].x, acc[ng][g]);
                    acc[ng][g] = ffma2(av.y, w[ng][cu].y, acc[ng][g]);
                }
            }
        }
    };

    LD(wA, 0);
#pragma unroll 1
    for (int cc = 0; cc < CH / 2; cc++) {
        LD(wB, 2 * cc + 1);
        CP(wA, 2 * cc);
        if (cc + 1 < CH / 2) LD(wA, 2 * cc + 2);
        CP(wB, 2 * cc + 1);
    }

#pragma unroll
    for (int ng = 0; ng < NG; ng++)
#pragma unroll
        for (int g = 0; g < G; g++) res[ng][g] = lanesum(acc[ng][g]);
}

// Per-matrix-activation variant (gate layer 2), CU=1.
template <int K2H, int NG, int N>
__device__ __forceinline__ void gemv_part_ma(
    float (&res)[NG][G],
    const ulonglong2* const (&Wv)[NG],
    const float* const (&av)[NG], int astride, int j)
{
    constexpr int CH = K2H / 2;
    static_assert(CH % 2 == 0, "chunks must be even");

    u64 acc[NG][G];
#pragma unroll
    for (int ng = 0; ng < NG; ng++)
#pragma unroll
        for (int g = 0; g < G; g++) acc[ng][g] = 0ull;

    ulonglong2 wA[NG], wB[NG];

    auto LD = [&](ulonglong2 (&w)[NG], int c) {
#pragma unroll
        for (int ng = 0; ng < NG; ng++) w[ng] = Wv[ng][c * N + j];
    };
    auto CP = [&](ulonglong2 (&w)[NG], int c) {
#pragma unroll
        for (int ng = 0; ng < NG; ng++) {
#pragma unroll
            for (int g = 0; g < G; g++) {
                ulonglong2 avv = *(const ulonglong2*)(av[ng] + g * astride + 4 * c);
                acc[ng][g] = ffma2(avv.x, w[ng].x, acc[ng][g]);
                acc[ng][g] = ffma2(avv.y, w[ng].y, acc[ng][g]);
            }
        }
    };

    LD(wA, 0);
#pragma unroll 1
    for (int cc = 0; cc < CH / 2; cc++) {
        LD(wB, 2 * cc + 1);
        CP(wA, 2 * cc);
        if (cc + 1 < CH / 2) LD(wA, 2 * cc + 2);
        CP(wB, 2 * cc + 1);
    }

#pragma unroll
    for (int ng = 0; ng < NG; ng++)
#pragma unroll
        for (int g = 0; g < G; g++) res[ng][g] = lanesum(acc[ng][g]);
}

// Decoder: one (output jd, trajectory) pair, half-K (32 k4 rows), N=128.
__device__ __forceinline__ float gemv_dec1(
    const ulonglong2* W, const float* act, int jd)
{
    constexpr int CU = 4, CH = 8;  // 32 k4 rows
    u64 acc = 0ull;
    ulonglong2 wA[CU], wB[CU];

    auto LD = [&](ulonglong2 (&w)[CU], int c) {
#pragma unroll
        for (int cu = 0; cu < CU; cu++) w[cu] = W[(c * CU + cu) * 128 + jd];
    };
    auto CP = [&](ulonglong2 (&w)[CU], int c) {
#pragma unroll
        for (int cu = 0; cu < CU; cu++) {
            int k4 = c * CU + cu;
            ulonglong2 a = *(const ulonglong2*)(act + 4 * k4);
            acc = ffma2(a.x, w[cu].x, acc);
            acc = ffma2(a.y, w[cu].y, acc);
        }
    };

    LD(wA, 0);
#pragma unroll 1
    for (int cc = 0; cc < CH / 2; cc++) {
        LD(wB, 2 * cc + 1);
        CP(wA, 2 * cc);
        if (cc + 1 < CH / 2) LD(wA, 2 * cc + 2);
        CP(wB, 2 * cc + 1);
    }
    return lanesum(acc);
}

// ---------------------------------------------------------------------------
// Shared memory layout (dynamic). ~62 KB
// Q[m][kq][g*128 + jloc] : all 4 kq store; combine reads conflict-free.
// ---------------------------------------------------------------------------
struct __align__(16) SM {
    float sy  [G * 256];        // full in both CTAs
    float syt [G * 256];        // full in both CTAs
    float syc [G * GIN];        // full in both CTAs
    float shh0[G * 256];
    float shh1[G * 256];
    float shh2[G * 256];
    float smean[G * 256];       // mean_ydec (local, replicated)
    float Q[3][4][G * 128];     // intra-CTA K-quarter partials (all kq write)
    float Pd[64][G];            // decoder kh1 partial
    float Dl[G], Dr[G];         // decay-L2 half sums (local / from peer)
    float sdt[G], smask[G], se1[G], se2[G];
    float sred16[16];
};
#define SMEM_BYTES ((int)sizeof(SM))

__global__ void __cluster_dims__(2, 1, 1) __launch_bounds__(THREADS, 1)
rnn_decay_kernel(
    const float* __restrict__ data, const float* __restrict__ ts,
    const float* __restrict__ ug_b1,  const float* __restrict__ ug_b2,
    const float* __restrict__ ugt_b1, const float* __restrict__ ugt_b2,
    const float* __restrict__ rg_b1,  const float* __restrict__ rg_b2,
    const float* __restrict__ ns_b1,  const float* __restrict__ ns_b2,
    const float* __restrict__ dk_b1,  const float* __restrict__ dk_w2,
    const float* __restrict__ dk_b2,  const float* __restrict__ dec_b,
    float* __restrict__ out)
{
    extern __shared__ __align__(16) char smraw[];
    SM* sm = reinterpret_cast<SM*>(smraw);

    const int tid  = threadIdx.x;        // 0..511
    const int jloc = tid & 127;          // gemv: output column within N-half
    const int kq   = tid >> 7;           // gemv: K-quarter 0..3
    const int lane = tid & 31, warp = tid >> 5;
    const uint32_t rank = ctarank();     // N-half owned by this CTA
    const int tb   = (blockIdx.x >> 1) * G;
    const int jglob = (int)rank * 128 + jloc;

    // combine mapping: one (gc, jc) pair per thread
    const int gc = tid >> 7, jc = tid & 127;
    const int jgc = (int)rank * 128 + jc;       // combine's global column
    const int cidx = gc * 256 + jgc;            // state index for combine thread
    const int qidx = gc * 128 + jc;             // Q index for combine thread

    const uint32_t sb = smem_u32(sm);
    const uint32_t pb = mapa_u32(sb, rank ^ 1u);
    const uint32_t pSy   = pb + (uint32_t)offsetof(SM, sy);
    const uint32_t pSyt  = pb + (uint32_t)offsetof(SM, syt);
    const uint32_t pSyc  = pb + (uint32_t)offsetof(SM, syc);
    const uint32_t pShh0 = pb + (uint32_t)offsetof(SM, shh0);
    const uint32_t pShh1 = pb + (uint32_t)offsetof(SM, shh1);
    const uint32_t pShh2 = pb + (uint32_t)offsetof(SM, shh2);
    const uint32_t pDr   = pb + (uint32_t)offsetof(SM, Dr);

    const ulonglong2* WP = g_wp;

    // K-quarter offsets
    const int r256q = kq * 16 * 256;
    const int a256q = kq * 64;
    const int r384q = kq * 24 * 256;
    const int a384q = kq * 96;

    // decoder mapping
    const int jd = tid & 63, gd = (tid >> 6) & 3, kh = tid >> 8;
    const int jdglob = (int)rank * 64 + jd;

    float* out_prev = out;
    float* out_vol  = out + (size_t)NTRAJ * LATENT;
    float* out_dts  = out + (size_t)NTRAJ * LATENT + (size_t)NTRAJ * NSTEP * DEC_OUT;

    for (int i = tid; i < G * 256; i += THREADS) { sm->sy[i] = 0.f; sm->syt[i] = 0.f; }

    for (int t = 0; t < NTP; t++) {
        CLUSTER_SYNC();   // S0: state exchange visible; buffer reuse protected

        // ---- setup: xh -> syc tail (full), mask, dt ----
        {
            int g = tid >> 7, jj = tid & 127;
            sm->syc[g * GIN + LATENT + jj] =
                data[((size_t)(tb + g) * NTP + t) * (2 * INPUT) + jj];
        }
        if (warp < G) {
            const float* xp = data + ((size_t)(tb + warp) * NTP + t) * (2 * INPUT) + INPUT;
            float s = xp[lane] + xp[lane + 32] + xp[lane + 64] + xp[lane + 96];
#pragma unroll
            for (int off = 16; off; off >>= 1) s += __shfl_xor_sync(0xffffffffu, s, off);
            if (lane == 0) sm->smask[warp] = (s > 0.f) ? 1.f : 0.f;
        }
        if (tid < G && t > 0) {
            float d = ts[(size_t)(tb + tid) * NTP + t] - ts[(size_t)(tb + tid) * NTP + t - 1];
            sm->sdt[tid] = d;
            if (rank == 0)
                out_dts[(size_t)(tb + tid) * NSTEP + (t - 1)] = d;
        }
        __syncthreads();

        float uu = 0.f, uut = 0.f;   // combine-thread gate values (gc, jgc)
        float pdec = 0.f;

        if (t > 0) {
            // ---- decay layer1 (own N-half, K via kq quarters) ----
            {
                const ulonglong2* Wd[1] = { WP + OFF_DK1 + r256q };
                float p[1][G];
                gemv_part<32, 1, 256, 4>(p, Wd, sm->sy + a256q, 256, jglob);
#pragma unroll
                for (int g = 0; g < G; g++) sm->Q[0][kq][g * 128 + jloc] = p[0][g];
                __syncthreads();
                // spread combine + fused decay-L2 reduction
                float s = sm->Q[0][0][qidx] + sm->Q[0][1][qidx]
                        + sm->Q[0][2][qidx] + sm->Q[0][3][qidx];
                float v = fmaxf(s + dk_b1[jgc], 0.f) * dk_w2[jgc];
#pragma unroll
                for (int off = 16; off; off >>= 1)
                    v += __shfl_xor_sync(0xffffffffu, v, off);
                if (lane == 0) sm->sred16[warp] = v;
                __syncthreads();
                if (tid < G) {
                    float ss = sm->sred16[4 * tid] + sm->sred16[4 * tid + 1]
                             + sm->sred16[4 * tid + 2] + sm->sred16[4 * tid + 3];
                    sm->Dl[tid] = ss;
                    st_peer_f1(pDr + (uint32_t)tid * 4u, ss);
                }
            }
            CLUSTER_SYNC();  // CS1
            if (tid < G) {
                float dec = fmaxf(sm->Dl[tid] + sm->Dr[tid] + dk_b2[0], 0.f);
                float d = dec * sm->sdt[tid];
                sm->se1[tid] = __expf(-0.5f * d);
                sm->se2[tid] = __expf(-d);
            }
            __syncthreads();

            // ---- elementwise decay (replicated in both CTAs) ----
            for (int it = tid; it < G * 256; it += THREADS) {
                int g = it >> 8, jj = it & 255;
                float yv = sm->sy[g * 256 + jj], ytv = sm->syt[g * 256 + jj];
                float df = yv - ytv;
                sm->smean[g * 256 + jj] = ytv + df * (0.5f * (1.f + sm->se1[g]));
                float ye = ytv + df * sm->se2[g];
                sm->sy[g * 256 + jj] = ye;
                sm->syc[g * GIN + jj] = ye;
            }
            __syncthreads();

            // ---- decoder partial (own 64 columns, half-K per kh) ----
            {
                const ulonglong2* Wd = WP + OFF_DEC + kh * 32 * 128;
                pdec = gemv_dec1(Wd, sm->smean + gd * 256 + kh * 128, jdglob);
                if (kh) sm->Pd[jd][gd] = pdec;
            }
        } else {
            for (int it = tid; it < G * 256; it += THREADS) {
                int g = it >> 8, jj = it & 255;
                sm->syc[g * GIN + jj] = 0.f;
            }
            __syncthreads();
        }

        // ---- gate layer1: ug/ugt/rg fused (384->own 128 cols) ----
        {
            const ulonglong2* Wg[3] = { WP + OFF_UG1  + r384q,
                                        WP + OFF_UGT1 + r384q,
                                        WP + OFF_RG1  + r384q };
            float p[3][G];
            gemv_part<48, 3, 256, 1>(p, Wg, sm->syc + a384q, GIN, jglob);
#pragma unroll
            for (int m = 0; m < 3; m++)
#pragma unroll
                for (int g = 0; g < G; g++)
                    sm->Q[m][kq][g * 128 + jloc] = p[m][g];
            __syncthreads();   // also publishes Pd
            // decoder finalize (tid<256 = kh0), overlapped with combine
            if (t > 0 && kh == 0) {
                float v = pdec + sm->Pd[jd][gd] + dec_b[jdglob];
                out_vol[((size_t)(tb + gd) * NSTEP + (t - 1)) * DEC_OUT + jdglob] = v;
            }
            // spread combine: each thread one (gc, jgc), m = 0..2
            {
                const float* B1[3] = { ug_b1, ugt_b1, rg_b1 };
                float* SH[3] = { sm->shh0, sm->shh1, sm->shh2 };
                const uint32_t PSH[3] = { pShh0, pShh1, pShh2 };
#pragma unroll
                for (int m = 0; m < 3; m++) {
                    float s = sm->Q[m][0][qidx] + sm->Q[m][1][qidx]
                            + sm->Q[m][2][qidx] + sm->Q[m][3][qidx];
                    float a = tanhf(s + B1[m][jgc]);
                    SH[m][cidx] = a;
                    st_peer_f1(PSH[m] + (uint32_t)cidx * 4u, a);
                }
            }
        }
        CLUSTER_SYNC();  // CS2

        // ---- gate layer2 x3 (256->own 128 cols), per-matrix acts ----
        {
            const ulonglong2* Wg[3] = { WP + OFF_UG2  + r256q,
                                        WP + OFF_UGT2 + r256q,
                                        WP + OFF_RG2  + r256q };
            const float* av[3] = { sm->shh0 + a256q, sm->shh1 + a256q, sm->shh2 + a256q };
            float p[3][G];
            gemv_part_ma<32, 3, 256>(p, Wg, av, 256, jglob);
#pragma unroll
            for (int m = 0; m < 3; m++)
#pragma unroll
                for (int g = 0; g < G; g++)
                    sm->Q[m][kq][g * 128 + jloc] = p[m][g];
            __syncthreads();
            // spread combine
            {
                float s0 = sm->Q[0][0][qidx] + sm->Q[0][1][qidx]
                         + sm->Q[0][2][qidx] + sm->Q[0][3][qidx];
                float s1 = sm->Q[1][0][qidx] + sm->Q[1][1][qidx]
                         + sm->Q[1][2][qidx] + sm->Q[1][3][qidx];
                float s2 = sm->Q[2][0][qidx] + sm->Q[2][1][qidx]
                         + sm->Q[2][2][qidx] + sm->Q[2][3][qidx];
                uu  = sigmoid_fast(s0 + ug_b2[jgc]);
                uut = sigmoid_fast(s1 + ugt_b2[jgc]);
                float rr = sigmoid_fast(s2 + rg_b2[jgc]);
                int idx = gc * GIN + jgc;
                float v = sm->syc[idx] * rr;
                sm->syc[idx] = v;
                st_peer_f1(pSyc + (uint32_t)idx * 4u, v);
            }
        }
        CLUSTER_SYNC();  // CS3

        // ---- new_state layer1 (384->own 128 cols) ----
        {
            const ulonglong2* Wg[1] = { WP + OFF_NS1 + r384q };
            float p[1][G];
            gemv_part<48, 1, 256, 4>(p, Wg, sm->syc + a384q, GIN, jglob);
#pragma unroll
            for (int g = 0; g < G; g++) sm->Q[0][kq][g * 128 + jloc] = p[0][g];
            __syncthreads();
            {
                float s = sm->Q[0][0][qidx] + sm->Q[0][1][qidx]
                        + sm->Q[0][2][qidx] + sm->Q[0][3][qidx];
                float a = tanhf(s + ns_b1[jgc]);
                sm->shh0[cidx] = a;
                st_peer_f1(pShh0 + (uint32_t)cidx * 4u, a);
            }
        }
        CLUSTER_SYNC();  // CS4

        // ---- new_state layer2 (256->own 128 cols) + masked update ----
        {
            const ulonglong2* Wg[1] = { WP + OFF_NS2 + r256q };
            float p[1][G];
            gemv_part<32, 1, 256, 4>(p, Wg, sm->shh0 + a256q, 256, jglob);
#pragma unroll
            for (int g = 0; g < G; g++) sm->Q[0][kq][g * 128 + jloc] = p[0][g];
            __syncthreads();
            {
                float s = sm->Q[0][0][qidx] + sm->Q[0][1][qidx]
                        + sm->Q[0][2][qidx] + sm->Q[0][3][qidx];
                float nsv = s + ns_b2[jgc];
                float m    = sm->smask[gc];
                float yend = sm->sy[cidx], ytv = sm->syt[cidx];
                float ny   = (1.f - uu)  * nsv + uu  * yend;
                float nyt  = (1.f - uut) * nsv + uut * ytv;
                float oy   = m * ny  + (1.f - m) * yend;
                float oyt  = m * nyt + (1.f - m) * ytv;
                sm->sy[cidx]  = oy;
                sm->syt[cidx] = oyt;
                st_peer_f1(pSy  + (uint32_t)cidx * 4u, oy);
                st_peer_f1(pSyt + (uint32_t)cidx * 4u, oyt);
            }
        }
        // next S0 publishes state + protects Q/Pd/act reuse
    }

    CLUSTER_SYNC();
    if (rank == 0 && tid < 256) {
#pragma unroll
        for (int g = 0; g < G; g++)
            out_prev[(size_t)(tb + g) * LATENT + tid] = sm->sy[g * 256 + tid];
    }
}

extern "C" void kernel_launch(void* const* d_in, const int* in_sizes, int n_in,
                              void* d_out, int out_size) {
    const float* data   = (const float*)d_in[0];
    const float* ts     = (const float*)d_in[1];
    const float* ug_w1  = (const float*)d_in[2];
    const float* ug_b1  = (const float*)d_in[3];
    const float* ug_w2  = (const float*)d_in[4];
    const float* ug_b2  = (const float*)d_in[5];
    const float* ugt_w1 = (const float*)d_in[6];
    const float* ugt_b1 = (const float*)d_in[7];
    const float* ugt_w2 = (const float*)d_in[8];
    const float* ugt_b2 = (const float*)d_in[9];
    const float* rg_w1  = (const float*)d_in[10];
    const float* rg_b1  = (const float*)d_in[11];
    const float* rg_w2  = (const float*)d_in[12];
    const float* rg_b2  = (const float*)d_in[13];
    // d_in[14..17] = rgt_* : unused by the reference
    const float* ns_w1  = (const float*)d_in[18];
    const float* ns_b1  = (const float*)d_in[19];
    const float* ns_w2  = (const float*)d_in[20];
    const float* ns_b2  = (const float*)d_in[21];
    const float* dk_w1  = (const float*)d_in[22];
    const float* dk_b1  = (const float*)d_in[23];
    const float* dk_w2  = (const float*)d_in[24];
    const float* dk_b2  = (const float*)d_in[25];
    const float* dec_w  = (const float*)d_in[26];
    const float* dec_b  = (const float*)d_in[27];

    cudaFuncSetAttribute(rnn_decay_kernel,
                         cudaFuncAttributeMaxDynamicSharedMemorySize, SMEM_BYTES);

    pack_kernel<<<(WP_TOTAL + 255) / 256, 256>>>(
        ug_w1, ugt_w1, rg_w1, ns_w1, ug_w2, ugt_w2, rg_w2, ns_w2, dk_w1, dec_w);

    rnn_decay_kernel<<<NBLK, THREADS, SMEM_BYTES>>>(
        data, ts,
        ug_b1, ug_b2, ugt_b1, ugt_b2, rg_b1, rg_b2,
        ns_b1, ns_b2, dk_b1, dk_w2, dk_b2, dec_b,
        (float*)d_out);
}

// round 14
// speedup vs baseline: 1.0494x; 1.0494x over previous
#include <cuda_runtime.h>
#include <cuda_bf16.h>
#include <math.h>
#include <stdint.h>
#include <stddef.h>

#define NTRAJ  256
#define NTP    512
#define LATENT 256
#define INPUT  128
#define NUNITS 256
#define GIN    (LATENT + INPUT)   // 384
#define DEC_OUT 128
#define NSTEP  (NTP - 1)          // 511

#define G       4                 // trajectories per cluster
#define NCLU    (NTRAJ / G)       // 64 clusters
#define NBLK    (NCLU * 2)        // 128 CTAs (2 per cluster, N-split)
#define THREADS 512               // intra-CTA split-K x4 (kq groups)

typedef unsigned long long u64;

union F2U { float2 f; u64 u; };

__device__ __forceinline__ u64 ffma2(u64 a, u64 b, u64 c) {
    u64 d;
    asm("fma.rn.f32x2 %0, %1, %2, %3;" : "=l"(d) : "l"(a), "l"(b), "l"(c));
    return d;
}
__device__ __forceinline__ float lanesum(u64 v) {
    F2U r; r.u = v; return r.f.x + r.f.y;
}
__device__ __forceinline__ float sigmoid_fast(float x) {
    return __fdividef(1.f, 1.f + __expf(-x));
}
__device__ __forceinline__ uint32_t smem_u32(const void* p) {
    uint32_t a;
    asm("{ .reg .u64 t; cvta.to.shared.u64 t, %1; cvt.u32.u64 %0, t; }" : "=r"(a) : "l"(p));
    return a;
}
__device__ __forceinline__ uint32_t ctarank() {
    uint32_t r; asm("mov.u32 %0, %%cluster_ctarank;" : "=r"(r)); return r;
}
__device__ __forceinline__ uint32_t mapa_u32(uint32_t addr, uint32_t rank) {
    uint32_t r;
    asm("mapa.shared::cluster.u32 %0, %1, %2;" : "=r"(r) : "r"(addr), "r"(rank));
    return r;
}
__device__ __forceinline__ void st_peer_f1(uint32_t dst, float v) {
    asm volatile("st.shared::cluster.u32 [%0], %1;" :: "r"(dst), "f"(v) : "memory");
}
__device__ __forceinline__ void pf_l1(const void* p) {
    asm volatile("prefetch.global.L1 [%0];" :: "l"(p));
}
#define CLUSTER_SYNC() do { \
    asm volatile("barrier.cluster.arrive.aligned;" ::: "memory"); \
    asm volatile("barrier.cluster.wait.aligned;"   ::: "memory"); \
} while (0)

// ---------------------------------------------------------------------------
// Packed weights: float4 along k: W4[k4][j] = W[4k4..4k4+3][j], as ulonglong2.
// ---------------------------------------------------------------------------
#define SZ_M384 (96 * 256)
#define SZ_M256 (64 * 256)
#define SZ_DEC  (64 * 128)
#define OFF_UG1  0
#define OFF_UGT1 (OFF_UG1  + SZ_M384)
#define OFF_RG1  (OFF_UGT1 + SZ_M384)
#define OFF_NS1  (OFF_RG1  + SZ_M384)
#define OFF_UG2  (OFF_NS1  + SZ_M384)
#define OFF_UGT2 (OFF_UG2  + SZ_M256)
#define OFF_RG2  (OFF_UGT2 + SZ_M256)
#define OFF_NS2  (OFF_RG2  + SZ_M256)
#define OFF_DK1  (OFF_NS2  + SZ_M256)
#define OFF_DEC  (OFF_DK1  + SZ_M256)
#define WP_TOTAL (OFF_DEC  + SZ_DEC)

__device__ ulonglong2 g_wp[WP_TOTAL];

__global__ void pack_kernel(
    const float* ug1, const float* ugt1, const float* rg1, const float* ns1,
    const float* ug2, const float* ugt2, const float* rg2, const float* ns2,
    const float* dk1, const float* decw)
{
    const float* srcs[10] = {ug1, ugt1, rg1, ns1, ug2, ugt2, rg2, ns2, dk1, decw};
    const int offs[11] = {OFF_UG1, OFF_UGT1, OFF_RG1, OFF_NS1, OFF_UG2, OFF_UGT2,
                          OFF_RG2, OFF_NS2, OFF_DK1, OFF_DEC, WP_TOTAL};
    const int Ns[10] = {256,256,256,256,256,256,256,256,256,128};

    int idx = blockIdx.x * blockDim.x + threadIdx.x;
    if (idx >= WP_TOTAL) return;
    int m = 0;
    while (idx >= offs[m + 1]) m++;
    int local = idx - offs[m];
    int N = Ns[m];
    int k4 = local / N, j = local % N;
    const float* S = srcs[m];
    F2U lo, hi;
    lo.f = make_float2(S[(4 * k4 + 0) * N + j], S[(4 * k4 + 1) * N + j]);
    hi.f = make_float2(S[(4 * k4 + 2) * N + j], S[(4 * k4 + 3) * N + j]);
    g_wp[idx] = make_ulonglong2(lo.u, hi.u);
}

// ---------------------------------------------------------------------------
// Partial packed GEMV (quarter-K), shared activation. A/B register buffer.
// ---------------------------------------------------------------------------
template <int K2H, int NG, int N, int CU>
__device__ __forceinline__ void gemv_part(
    float (&res)[NG][G],
    const ulonglong2* const (&Wv)[NG],
    const float* act, int astride, int j)
{
    constexpr int K4 = K2H / 2;
    constexpr int CH = K4 / CU;
    static_assert(CH % 2 == 0, "chunks must be even");

    u64 acc[NG][G];
#pragma unroll
    for (int ng = 0; ng < NG; ng++)
#pragma unroll
        for (int g = 0; g < G; g++) acc[ng][g] = 0ull;

    ulonglong2 wA[NG][CU], wB[NG][CU];

    auto LD = [&](ulonglong2 (&w)[NG][CU], int c) {
#pragma unroll
        for (int ng = 0; ng < NG; ng++)
#pragma unroll
            for (int cu = 0; cu < CU; cu++)
                w[ng][cu] = Wv[ng][(c * CU + cu) * N + j];
    };
    auto CP = [&](ulonglong2 (&w)[NG][CU], int c) {
#pragma unroll
        for (int cu = 0; cu < CU; cu++) {
            int k4 = c * CU + cu;
#pragma unroll
            for (int g = 0; g < G; g++) {
                ulonglong2 av = *(const ulonglong2*)(act + g * astride + 4 * k4);
#pragma unroll
                for (int ng = 0; ng < NG; ng++) {
                    acc[ng][g] = ffma2(av.x, w[ng][cu].x, acc[ng][g]);
                    acc[ng][g] = ffma2(av.y, w[ng][cu].y, acc[ng][g]);
                }
            }
        }
    };

    LD(wA, 0);
#pragma unroll 1
    for (int cc = 0; cc < CH / 2; cc++) {
        LD(wB, 2 * cc + 1);
        CP(wA, 2 * cc);
        if (cc + 1 < CH / 2) LD(wA, 2 * cc + 2);
        CP(wB, 2 * cc + 1);
    }

#pragma unroll
    for (int ng = 0; ng < NG; ng++)
#pragma unroll
        for (int g = 0; g < G; g++) res[ng][g] = lanesum(acc[ng][g]);
}

// Per-matrix-activation variant (gate layer 2), CU=1.
template <int K2H, int NG, int N>
__device__ __forceinline__ void gemv_part_ma(
    float (&res)[NG][G],
    const ulonglong2* const (&Wv)[NG],
    const float* const (&av)[NG], int astride, int j)
{
    constexpr int CH = K2H / 2;
    static_assert(CH % 2 == 0, "chunks must be even");

    u64 acc[NG][G];
#pragma unroll
    for (int ng = 0; ng < NG; ng++)
#pragma unroll
        for (int g = 0; g < G; g++) acc[ng][g] = 0ull;

    ulonglong2 wA[NG], wB[NG];

    auto LD = [&](ulonglong2 (&w)[NG], int c) {
#pragma unroll
        for (int ng = 0; ng < NG; ng++) w[ng] = Wv[ng][c * N + j];
    };
    auto CP = [&](ulonglong2 (&w)[NG], int c) {
#pragma unroll
        for (int ng = 0; ng < NG; ng++) {
#pragma unroll
            for (int g = 0; g < G; g++) {
                ulonglong2 avv = *(const ulonglong2*)(av[ng] + g * astride + 4 * c);
                acc[ng][g] = ffma2(avv.x, w[ng].x, acc[ng][g]);
                acc[ng][g] = ffma2(avv.y, w[ng].y, acc[ng][g]);
            }
        }
    };

    LD(wA, 0);
#pragma unroll 1
    for (int cc = 0; cc < CH / 2; cc++) {
        LD(wB, 2 * cc + 1);
        CP(wA, 2 * cc);
        if (cc + 1 < CH / 2) LD(wA, 2 * cc + 2);
        CP(wB, 2 * cc + 1);
    }

#pragma unroll
    for (int ng = 0; ng < NG; ng++)
#pragma unroll
        for (int g = 0; g < G; g++) res[ng][g] = lanesum(acc[ng][g]);
}

// Decoder: one (output jd, trajectory) pair, half-K (32 k4 rows), N=128.
__device__ __forceinline__ float gemv_dec1(
    const ulonglong2* W, const float* act, int jd)
{
    constexpr int CU = 4, CH = 8;  // 32 k4 rows
    u64 acc = 0ull;
    ulonglong2 wA[CU], wB[CU];

    auto LD = [&](ulonglong2 (&w)[CU], int c) {
#pragma unroll
        for (int cu = 0; cu < CU; cu++) w[cu] = W[(c * CU + cu) * 128 + jd];
    };
    auto CP = [&](ulonglong2 (&w)[CU], int c) {
#pragma unroll
        for (int cu = 0; cu < CU; cu++) {
            int k4 = c * CU + cu;
            ulonglong2 a = *(const ulonglong2*)(act + 4 * k4);
            acc = ffma2(a.x, w[cu].x, acc);
            acc = ffma2(a.y, w[cu].y, acc);
        }
    };

    LD(wA, 0);
#pragma unroll 1
    for (int cc = 0; cc < CH / 2; cc++) {
        LD(wB, 2 * cc + 1);
        CP(wA, 2 * cc);
        if (cc + 1 < CH / 2) LD(wA, 2 * cc + 2);
        CP(wB, 2 * cc + 1);
    }
    return lanesum(acc);
}

// ---------------------------------------------------------------------------
// Shared memory layout (dynamic). ~95 KB
// ---------------------------------------------------------------------------
struct __align__(16) SM {
    float sy  [G * 256];        // full in both CTAs
    float syt [G * 256];        // full in both CTAs
    float syc [G * GIN];        // full in both CTAs
    float shh0[G * 256];
    float shh1[G * 256];
    float shh2[G * 256];
    float smean[G * 256];       // mean_ydec (local, replicated)
    float Q[3][3][128][G];      // intra-CTA K-quarter partials (kq 0..2 write)
    float Qx[4][4][128][G];     // xh pre-partials [matrix][kq] (all kq write)
    float Pd[64][G];            // decoder kh1 partial
    float Dl[G], Dr[G];         // decay-L2 half sums (local / from peer)
    float sdt[G], smask[G], se1[G], se2[G];
    float sred[4][G];
};
#define SMEM_BYTES ((int)sizeof(SM))

__global__ void __cluster_dims__(2, 1, 1) __launch_bounds__(THREADS, 1)
rnn_decay_kernel(
    const float* __restrict__ data, const float* __restrict__ ts,
    const float* __restrict__ ug_b1,  const float* __restrict__ ug_b2,
    const float* __restrict__ ugt_b1, const float* __restrict__ ugt_b2,
    const float* __restrict__ rg_b1,  const float* __restrict__ rg_b2,
    const float* __restrict__ ns_b1,  const float* __restrict__ ns_b2,
    const float* __restrict__ dk_b1,  const float* __restrict__ dk_w2,
    const float* __restrict__ dk_b2,  const float* __restrict__ dec_b,
    float* __restrict__ out)
{
    extern __shared__ __align__(16) char smraw[];
    SM* sm = reinterpret_cast<SM*>(smraw);

    const int tid  = threadIdx.x;        // 0..511
    const int jloc = tid & 127;          // output column within this CTA's half
    const int kq   = tid >> 7;           // K-quarter 0..3
    const int lane = tid & 31, warp = tid >> 5;
    const uint32_t rank = ctarank();     // N-half owned by this CTA
    const int tb   = (blockIdx.x >> 1) * G;
    const int jglob = (int)rank * 128 + jloc;

    const uint32_t sb = smem_u32(sm);
    const uint32_t pb = mapa_u32(sb, rank ^ 1u);
    const uint32_t pSy   = pb + (uint32_t)offsetof(SM, sy);
    const uint32_t pSyt  = pb + (uint32_t)offsetof(SM, syt);
    const uint32_t pSyc  = pb + (uint32_t)offsetof(SM, syc);
    const uint32_t pShh0 = pb + (uint32_t)offsetof(SM, shh0);
    const uint32_t pShh1 = pb + (uint32_t)offsetof(SM, shh1);
    const uint32_t pShh2 = pb + (uint32_t)offsetof(SM, shh2);
    const uint32_t pDr   = pb + (uint32_t)offsetof(SM, Dr);

    const ulonglong2* WP = g_wp;

    // K-quarter offsets
    const int r256q = kq * 16 * 256;     // 256-row matrices: 16 k4/quarter
    const int a256q = kq * 64;
    const int rxh   = (64 + kq * 8) * 256;  // xh rows of 384-row matrices
    const int axh   = LATENT + kq * 32;     // xh act offset in syc

    // decoder mapping
    const int jd = tid & 63, gd = (tid >> 6) & 3, kh = tid >> 8;
    const int jdglob = (int)rank * 64 + jd;

    float* out_prev = out;
    float* out_vol  = out + (size_t)NTRAJ * LATENT;
    float* out_dts  = out + (size_t)NTRAJ * LATENT + (size_t)NTRAJ * NSTEP * DEC_OUT;

    for (int i = tid; i < G * 256; i += THREADS) { sm->sy[i] = 0.f; sm->syt[i] = 0.f; }

    for (int t = 0; t < NTP; t++) {
        CLUSTER_SYNC();   // S0: state exchange visible; buffer reuse protected

        // ---- setup: xh -> syc tail (full), mask, dt ----
        {
            int g = tid >> 7, jj = tid & 127;
            sm->syc[g * GIN + LATENT + jj] =
                data[((size_t)(tb + g) * NTP + t) * (2 * INPUT) + jj];
        }
        if (warp < G) {
            const float* xp = data + ((size_t)(tb + warp) * NTP + t) * (2 * INPUT) + INPUT;
            float s = xp[lane] + xp[lane + 32] + xp[lane + 64] + xp[lane + 96];
#pragma unroll
            for (int off = 16; off; off >>= 1) s += __shfl_xor_sync(0xffffffffu, s, off);
            if (lane == 0) sm->smask[warp] = (s > 0.f) ? 1.f : 0.f;
        }
        if (tid < G && t > 0) {
            float d = ts[(size_t)(tb + tid) * NTP + t] - ts[(size_t)(tb + tid) * NTP + t - 1];
            sm->sdt[tid] = d;
            if (rank == 0)
                out_dts[(size_t)(tb + tid) * NSTEP + (t - 1)] = d;
        }
        __syncthreads();

        float u[G], ut[G];   // live in kq3 threads after gate2 combine
        float pdec = 0.f;

        // ---- xh pre-partials: ug1/ugt1/rg1/ns1 xh-rows (shared act) ----
        {
            const ulonglong2* Wx[4] = { WP + OFF_UG1  + rxh, WP + OFF_UGT1 + rxh,
                                        WP + OFF_RG1  + rxh, WP + OFF_NS1  + rxh };
            float px[4][G];
            gemv_part<16, 4, 256, 1>(px, Wx, sm->syc + axh, GIN, jglob);
#pragma unroll
            for (int m = 0; m < 4; m++)
                *(float4*)&sm->Qx[m][kq][jloc][0] =
                    make_float4(px[m][0], px[m][1], px[m][2], px[m][3]);
        }

        if (t > 0) {
            // ---- decay layer1 (own N-half, full K via kq quarters) ----
            {
                const ulonglong2* Wd[1] = { WP + OFF_DK1 + r256q };
                float p[1][G];
                gemv_part<32, 1, 256, 4>(p, Wd, sm->sy + a256q, 256, jglob);
                if (kq != 3)
                    *(float4*)&sm->Q[0][kq][jloc][0] =
                        make_float4(p[0][0], p[0][1], p[0][2], p[0][3]);
                __syncthreads();
                if (kq == 3) {
                    float bv = dk_b1[jglob];
                    float w2v = dk_w2[jglob];
                    float4 q0 = *(const float4*)&sm->Q[0][0][jloc][0];
                    float4 q1 = *(const float4*)&sm->Q[0][1][jloc][0];
                    float4 q2 = *(const float4*)&sm->Q[0][2][jloc][0];
                    float v[G];
                    v[0] = fmaxf(p[0][0] + q0.x + q1.x + q2.x + bv, 0.f) * w2v;
                    v[1] = fmaxf(p[0][1] + q0.y + q1.y + q2.y + bv, 0.f) * w2v;
                    v[2] = fmaxf(p[0][2] + q0.z + q1.z + q2.z + bv, 0.f) * w2v;
                    v[3] = fmaxf(p[0][3] + q0.w + q1.w + q2.w + bv, 0.f) * w2v;
#pragma unroll
                    for (int off = 16; off; off >>= 1)
#pragma unroll
                        for (int g = 0; g < G; g++)
                            v[g] += __shfl_xor_sync(0xffffffffu, v[g], off);
                    if (lane == 0)
#pragma unroll
                        for (int g = 0; g < G; g++) sm->sred[warp & 3][g] = v[g];
                }
                __syncthreads();
                if (tid < G) {
                    float s = sm->sred[0][tid] + sm->sred[1][tid]
                            + sm->sred[2][tid] + sm->sred[3][tid];
                    sm->Dl[tid] = s;
                    st_peer_f1(pDr + (uint32_t)tid * 4u, s);
                }
            }
            CLUSTER_SYNC();  // CS1
            if (tid < G) {
                float dec = fmaxf(sm->Dl[tid] + sm->Dr[tid] + dk_b2[0], 0.f);
                float d = dec * sm->sdt[tid];
                sm->se1[tid] = __expf(-0.5f * d);
                sm->se2[tid] = __expf(-d);
            }
            __syncthreads();

            // ---- elementwise decay (replicated in both CTAs) ----
            for (int it = tid; it < G * 256; it += THREADS) {
                int g = it >> 8, jj = it & 255;
                float yv = sm->sy[g * 256 + jj], ytv = sm->syt[g * 256 + jj];
                float df = yv - ytv;
                sm->smean[g * 256 + jj] = ytv + df * (0.5f * (1.f + sm->se1[g]));
                float ye = ytv + df * sm->se2[g];
                sm->sy[g * 256 + jj] = ye;
                sm->syc[g * GIN + jj] = ye;
            }
            __syncthreads();

            // ---- decoder partial (own 64 columns, half-K per kh) ----
            {
                const ulonglong2* Wd = WP + OFF_DEC + kh * 32 * 128;
                pdec = gemv_dec1(Wd, sm->smean + gd * 256 + kh * 128, jdglob);
                if (kh) sm->Pd[jd][gd] = pdec;
            }
        } else {
            for (int it = tid; it < G * 256; it += THREADS) {
                int g = it >> 8, jj = it & 255;
                sm->syc[g * GIN + jj] = 0.f;
            }
            __syncthreads();
        }

        // ---- gate layer1: ug/ugt/rg y-part (256->own 128 cols) ----
        {
            const ulonglong2* Wg[3] = { WP + OFF_UG1  + r256q,
                                        WP + OFF_UGT1 + r256q,
                                        WP + OFF_RG1  + r256q };
            float p[3][G];
            gemv_part<32, 3, 256, 2>(p, Wg, sm->syc + a256q, GIN, jglob);
            if (kq != 3) {
#pragma unroll
                for (int m = 0; m < 3; m++)
                    *(float4*)&sm->Q[m][kq][jloc][0] =
                        make_float4(p[m][0], p[m][1], p[m][2], p[m][3]);
            }
            __syncthreads();   // also publishes Pd
            if (kq == 3) {
                const float* B1[3] = { ug_b1, ugt_b1, rg_b1 };
                float* SH[3] = { sm->shh0, sm->shh1, sm->shh2 };
                const uint32_t PSH[3] = { pShh0, pShh1, pShh2 };
#pragma unroll
                for (int m = 0; m < 3; m++) {
                    float bv = B1[m][jglob];
                    float4 q0 = *(const float4*)&sm->Q[m][0][jloc][0];
                    float4 q1 = *(const float4*)&sm->Q[m][1][jloc][0];
                    float4 q2 = *(const float4*)&sm->Q[m][2][jloc][0];
                    float4 x0 = *(const float4*)&sm->Qx[m][0][jloc][0];
                    float4 x1 = *(const float4*)&sm->Qx[m][1][jloc][0];
                    float4 x2 = *(const float4*)&sm->Qx[m][2][jloc][0];
                    float4 x3 = *(const float4*)&sm->Qx[m][3][jloc][0];
                    float vv[G] = {
                        p[m][0] + q0.x + q1.x + q2.x + x0.x + x1.x + x2.x + x3.x + bv,
                        p[m][1] + q0.y + q1.y + q2.y + x0.y + x1.y + x2.y + x3.y + bv,
                        p[m][2] + q0.z + q1.z + q2.z + x0.z + x1.z + x2.z + x3.z + bv,
                        p[m][3] + q0.w + q1.w + q2.w + x0.w + x1.w + x2.w + x3.w + bv };
#pragma unroll
                    for (int g = 0; g < G; g++) {
                        float a = tanhf(vv[g]);
                        int idx = g * 256 + jglob;
                        SH[m][idx] = a;
                        st_peer_f1(PSH[m] + (uint32_t)idx * 4u, a);
                    }
                }
            } else if (t > 0 && kh == 0) {
                // decoder finalize -> global (own 64 columns)
                float v = pdec + sm->Pd[jd][gd] + dec_b[jdglob];
                out_vol[((size_t)(tb + gd) * NSTEP + (t - 1)) * DEC_OUT + jdglob] = v;
            }
            // warm next phase's first weight rows while waiting
            pf_l1(WP + OFF_UG2  + r256q + jglob);
            pf_l1(WP + OFF_UGT2 + r256q + jglob);
            pf_l1(WP + OFF_RG2  + r256q + jglob);
        }
        CLUSTER_SYNC();  // CS2

        // ---- gate layer2 x3 (256->own 128 cols), per-matrix acts ----
        {
            const ulonglong2* Wg[3] = { WP + OFF_UG2  + r256q,
                                        WP + OFF_UGT2 + r256q,
                                        WP + OFF_RG2  + r256q };
            const float* av[3] = { sm->shh0 + a256q, sm->shh1 + a256q, sm->shh2 + a256q };
            float p[3][G];
            gemv_part_ma<32, 3, 256>(p, Wg, av, 256, jglob);
            if (kq != 3) {
#pragma unroll
                for (int m = 0; m < 3; m++)
                    *(float4*)&sm->Q[m][kq][jloc][0] =
                        make_float4(p[m][0], p[m][1], p[m][2], p[m][3]);
            }
            __syncthreads();
            if (kq == 3) {
                float b0 = ug_b2[jglob], b1 = ugt_b2[jglob], b2 = rg_b2[jglob];
                float4 q0, q1, q2;
                q0 = *(const float4*)&sm->Q[0][0][jloc][0];
                q1 = *(const float4*)&sm->Q[0][1][jloc][0];
                q2 = *(const float4*)&sm->Q[0][2][jloc][0];
                u[0] = sigmoid_fast(p[0][0] + q0.x + q1.x + q2.x + b0);
                u[1] = sigmoid_fast(p[0][1] + q0.y + q1.y + q2.y + b0);
                u[2] = sigmoid_fast(p[0][2] + q0.z + q1.z + q2.z + b0);
                u[3] = sigmoid_fast(p[0][3] + q0.w + q1.w + q2.w + b0);
                q0 = *(const float4*)&sm->Q[1][0][jloc][0];
                q1 = *(const float4*)&sm->Q[1][1][jloc][0];
                q2 = *(const float4*)&sm->Q[1][2][jloc][0];
                ut[0] = sigmoid_fast(p[1][0] + q0.x + q1.x + q2.x + b1);
                ut[1] = sigmoid_fast(p[1][1] + q0.y + q1.y + q2.y + b1);
                ut[2] = sigmoid_fast(p[1][2] + q0.z + q1.z + q2.z + b1);
                ut[3] = sigmoid_fast(p[1][3] + q0.w + q1.w + q2.w + b1);
                q0 = *(const float4*)&sm->Q[2][0][jloc][0];
                q1 = *(const float4*)&sm->Q[2][1][jloc][0];
                q2 = *(const float4*)&sm->Q[2][2][jloc][0];
                float rr[G] = { sigmoid_fast(p[2][0] + q0.x + q1.x + q2.x + b2),
                                sigmoid_fast(p[2][1] + q0.y + q1.y + q2.y + b2),
                                sigmoid_fast(p[2][2] + q0.z + q1.z + q2.z + b2),
                                sigmoid_fast(p[2][3] + q0.w + q1.w + q2.w + b2) };
#pragma unroll
                for (int g = 0; g < G; g++) {
                    int idx = g * GIN + jglob;
                    float v = sm->syc[idx] * rr[g];
                    sm->syc[idx] = v;
                    st_peer_f1(pSyc + (uint32_t)idx * 4u, v);
                }
            }
            pf_l1(WP + OFF_NS1 + r256q + jglob);
            pf_l1(WP + OFF_NS1 + r256q + 256 + jglob);
        }
        CLUSTER_SYNC();  // CS3

        // ---- new_state layer1 y-part (256->own 128 cols) ----
        {
            const ulonglong2* Wg[1] = { WP + OFF_NS1 + r256q };
            float p[1][G];
            gemv_part<32, 1, 256, 4>(p, Wg, sm->syc + a256q, GIN, jglob);
            if (kq != 3)
                *(float4*)&sm->Q[0][kq][jloc][0] =
                    make_float4(p[0][0], p[0][1], p[0][2], p[0][3]);
            __syncthreads();
            if (kq == 3) {
                float bv = ns_b1[jglob];
                float4 q0 = *(const float4*)&sm->Q[0][0][jloc][0];
                float4 q1 = *(const float4*)&sm->Q[0][1][jloc][0];
                float4 q2 = *(const float4*)&sm->Q[0][2][jloc][0];
                float4 x0 = *(const float4*)&sm->Qx[3][0][jloc][0];
                float4 x1 = *(const float4*)&sm->Qx[3][1][jloc][0];
                float4 x2 = *(const float4*)&sm->Qx[3][2][jloc][0];
                float4 x3 = *(const float4*)&sm->Qx[3][3][jloc][0];
                float vv[G] = {
                    p[0][0] + q0.x + q1.x + q2.x + x0.x + x1.x + x2.x + x3.x + bv,
                    p[0][1] + q0.y + q1.y + q2.y + x0.y + x1.y + x2.y + x3.y + bv,
                    p[0][2] + q0.z + q1.z + q2.z + x0.z + x1.z + x2.z + x3.z + bv,
                    p[0][3] + q0.w + q1.w + q2.w + x0.w + x1.w + x2.w + x3.w + bv };
#pragma unroll
                for (int g = 0; g < G; g++) {
                    float a = tanhf(vv[g]);
                    int idx = g * 256 + jglob;
                    sm->shh0[idx] = a;
                    st_peer_f1(pShh0 + (uint32_t)idx * 4u, a);
                }
            }
            pf_l1(WP + OFF_NS2 + r256q + jglob);
            pf_l1(WP + OFF_NS2 + r256q + 256 + jglob);
        }
        CLUSTER_SYNC();  // CS4

        // ---- new_state layer2 (256->own 128 cols) + masked update ----
        {
            const ulonglong2* Wg[1] = { WP + OFF_NS2 + r256q };
            float p[1][G];
            gemv_part<32, 1, 256, 4>(p, Wg, sm->shh0 + a256q, 256, jglob);
            if (kq != 3)
                *(float4*)&sm->Q[0][kq][jloc][0] =
                    make_float4(p[0][0], p[0][1], p[0][2], p[0][3]);
            __syncthreads();
            if (kq == 3) {
                float bv = ns_b2[jglob];
                float4 q0 = *(const float4*)&sm->Q[0][0][jloc][0];
                float4 q1 = *(const float4*)&sm->Q[0][1][jloc][0];
                float4 q2 = *(const float4*)&sm->Q[0][2][jloc][0];
                float nsv[G] = { p[0][0] + q0.x + q1.x + q2.x + bv,
                                 p[0][1] + q0.y + q1.y + q2.y + bv,
                                 p[0][2] + q0.z + q1.z + q2.z + bv,
                                 p[0][3] + q0.w + q1.w + q2.w + bv };
#pragma unroll
                for (int g = 0; g < G; g++) {
                    float m    = sm->smask[g];
                    int idx    = g * 256 + jglob;
                    float yend = sm->sy[idx], ytv = sm->syt[idx];
                    float ny   = (1.f - u[g])  * nsv[g] + u[g]  * yend;
                    float nyt  = (1.f - ut[g]) * nsv[g] + ut[g] * ytv;
                    float oy   = m * ny  + (1.f - m) * yend;
                    float oyt  = m * nyt + (1.f - m) * ytv;
                    sm->sy[idx]  = oy;
                    sm->syt[idx] = oyt;
                    st_peer_f1(pSy  + (uint32_t)idx * 4u, oy);
                    st_peer_f1(pSyt + (uint32_t)idx * 4u, oyt);
                }
            }
        }
        // next S0 publishes state + protects Q/Qx/Pd/act reuse
    }

    CLUSTER_SYNC();
    if (rank == 0 && tid < 256) {
#pragma unroll
        for (int g = 0; g < G; g++)
            out_prev[(size_t)(tb + g) * LATENT + tid] = sm->sy[g * 256 + tid];
    }
}

extern "C" void kernel_launch(void* const* d_in, const int* in_sizes, int n_in,
                              void* d_out, int out_size) {
    const float* data   = (const float*)d_in[0];
    const float* ts     = (const float*)d_in[1];
    const float* ug_w1  = (const float*)d_in[2];
    const float* ug_b1  = (const float*)d_in[3];
    const float* ug_w2  = (const float*)d_in[4];
    const float* ug_b2  = (const float*)d_in[5];
    const float* ugt_w1 = (const float*)d_in[6];
    const float* ugt_b1 = (const float*)d_in[7];
    const float* ugt_w2 = (const float*)d_in[8];
    const float* ugt_b2 = (const float*)d_in[9];
    const float* rg_w1  = (const float*)d_in[10];
    const float* rg_b1  = (const float*)d_in[11];
    const float* rg_w2  = (const float*)d_in[12];
    const float* rg_b2  = (const float*)d_in[13];
    // d_in[14..17] = rgt_* : unused by the reference
    const float* ns_w1  = (const float*)d_in[18];
    const float* ns_b1  = (const float*)d_in[19];
    const float* ns_w2  = (const float*)d_in[20];
    const float* ns_b2  = (const float*)d_in[21];
    const float* dk_w1  = (const float*)d_in[22];
    const float* dk_b1  = (const float*)d_in[23];
    const float* dk_w2  = (const float*)d_in[24];
    const float* dk_b2  = (const float*)d_in[25];
    const float* dec_w  = (const float*)d_in[26];
    const float* dec_b  = (const float*)d_in[27];

    cudaFuncSetAttribute(rnn_decay_kernel,
                         cudaFuncAttributeMaxDynamicSharedMemorySize, SMEM_BYTES);

    pack_kernel<<<(WP_TOTAL + 255) / 256, 256>>>(
        ug_w1, ugt_w1, rg_w1, ns_w1, ug_w2, ugt_w2, rg_w2, ns_w2, dk_w1, dec_w);

    rnn_decay_kernel<<<NBLK, THREADS, SMEM_BYTES>>>(
        data, ts,
        ug_b1, ug_b2, ugt_b1, ugt_b2, rg_b1, rg_b2,
        ns_b1, ns_b2, dk_b1, dk_w2, dk_b2, dec_b,
        (float*)d_out);
}

// round 16
// speedup vs baseline: 1.0745x; 1.0239x over previous
#include <cuda_runtime.h>
#include <cuda_bf16.h>
#include <math.h>
#include <stdint.h>
#include <stddef.h>

#define NTRAJ  256
#define NTP    512
#define LATENT 256
#define INPUT  128
#define NUNITS 256
#define GIN    (LATENT + INPUT)   // 384
#define DEC_OUT 128
#define NSTEP  (NTP - 1)          // 511

#define G       4                 // trajectories per cluster
#define NCLU    (NTRAJ / G)       // 64 clusters
#define NBLK    (NCLU * 2)        // 128 CTAs (2 per cluster, N-split)
#define THREADS 512               // intra-CTA split-K x4 (kq groups)

typedef unsigned long long u64;

union F2U { float2 f; u64 u; };

__device__ __forceinline__ u64 ffma2(u64 a, u64 b, u64 c) {
    u64 d;
    asm("fma.rn.f32x2 %0, %1, %2, %3;" : "=l"(d) : "l"(a), "l"(b), "l"(c));
    return d;
}
__device__ __forceinline__ float lanesum(u64 v) {
    F2U r; r.u = v; return r.f.x + r.f.y;
}
__device__ __forceinline__ float sigmoid_fast(float x) {
    return __fdividef(1.f, 1.f + __expf(-x));
}
__device__ __forceinline__ uint32_t smem_u32(const void* p) {
    uint32_t a;
    asm("{ .reg .u64 t; cvta.to.shared.u64 t, %1; cvt.u32.u64 %0, t; }" : "=r"(a) : "l"(p));
    return a;
}
__device__ __forceinline__ uint32_t ctarank() {
    uint32_t r; asm("mov.u32 %0, %%cluster_ctarank;" : "=r"(r)); return r;
}
__device__ __forceinline__ uint32_t mapa_u32(uint32_t addr, uint32_t rank) {
    uint32_t r;
    asm("mapa.shared::cluster.u32 %0, %1, %2;" : "=r"(r) : "r"(addr), "r"(rank));
    return r;
}
__device__ __forceinline__ void st_peer_f1(uint32_t dst, float v) {
    asm volatile("st.shared::cluster.u32 [%0], %1;" :: "r"(dst), "f"(v) : "memory");
}
__device__ __forceinline__ void pf_l1(const void* p) {
    asm volatile("prefetch.global.L1 [%0];" :: "l"(p));
}
#define CLUSTER_ARRIVE() asm volatile("barrier.cluster.arrive.aligned;" ::: "memory")
#define CLUSTER_WAIT()   asm volatile("barrier.cluster.wait.aligned;"   ::: "memory")
#define CLUSTER_SYNC() do { CLUSTER_ARRIVE(); CLUSTER_WAIT(); } while (0)

// ---------------------------------------------------------------------------
// Packed weights: float4 along k: W4[k4][j] = W[4k4..4k4+3][j], as ulonglong2.
// ---------------------------------------------------------------------------
#define SZ_M384 (96 * 256)
#define SZ_M256 (64 * 256)
#define SZ_DEC  (64 * 128)
#define OFF_UG1  0
#define OFF_UGT1 (OFF_UG1  + SZ_M384)
#define OFF_RG1  (OFF_UGT1 + SZ_M384)
#define OFF_NS1  (OFF_RG1  + SZ_M384)
#define OFF_UG2  (OFF_NS1  + SZ_M384)
#define OFF_UGT2 (OFF_UG2  + SZ_M256)
#define OFF_RG2  (OFF_UGT2 + SZ_M256)
#define OFF_NS2  (OFF_RG2  + SZ_M256)
#define OFF_DK1  (OFF_NS2  + SZ_M256)
#define OFF_DEC  (OFF_DK1  + SZ_M256)
#define WP_TOTAL (OFF_DEC  + SZ_DEC)

__device__ ulonglong2 g_wp[WP_TOTAL];

__global__ void pack_kernel(
    const float* ug1, const float* ugt1, const float* rg1, const float* ns1,
    const float* ug2, const float* ugt2, const float* rg2, const float* ns2,
    const float* dk1, const float* decw)
{
    const float* srcs[10] = {ug1, ugt1, rg1, ns1, ug2, ugt2, rg2, ns2, dk1, decw};
    const int offs[11] = {OFF_UG1, OFF_UGT1, OFF_RG1, OFF_NS1, OFF_UG2, OFF_UGT2,
                          OFF_RG2, OFF_NS2, OFF_DK1, OFF_DEC, WP_TOTAL};
    const int Ns[10] = {256,256,256,256,256,256,256,256,256,128};

    int idx = blockIdx.x * blockDim.x + threadIdx.x;
    if (idx >= WP_TOTAL) return;
    int m = 0;
    while (idx >= offs[m + 1]) m++;
    int local = idx - offs[m];
    int N = Ns[m];
    int k4 = local / N, j = local % N;
    const float* S = srcs[m];
    F2U lo, hi;
    lo.f = make_float2(S[(4 * k4 + 0) * N + j], S[(4 * k4 + 1) * N + j]);
    hi.f = make_float2(S[(4 * k4 + 2) * N + j], S[(4 * k4 + 3) * N + j]);
    g_wp[idx] = make_ulonglong2(lo.u, hi.u);
}

// ---------------------------------------------------------------------------
// Partial packed GEMV (K-slice), shared activation. A/B register buffer.
// ---------------------------------------------------------------------------
template <int K2H, int NG, int N, int CU>
__device__ __forceinline__ void gemv_part(
    float (&res)[NG][G],
    const ulonglong2* const (&Wv)[NG],
    const float* act, int astride, int j)
{
    constexpr int K4 = K2H / 2;
    constexpr int CH = K4 / CU;
    static_assert(CH % 2 == 0, "chunks must be even");

    u64 acc[NG][G];
#pragma unroll
    for (int ng = 0; ng < NG; ng++)
#pragma unroll
        for (int g = 0; g < G; g++) acc[ng][g] = 0ull;

    ulonglong2 wA[NG][CU], wB[NG][CU];

    auto LD = [&](ulonglong2 (&w)[NG][CU], int c) {
#pragma unroll
        for (int ng = 0; ng < NG; ng++)
#pragma unroll
            for (int cu = 0; cu < CU; cu++)
                w[ng][cu] = Wv[ng][(c * CU + cu) * N + j];
    };
    auto CP = [&](ulonglong2 (&w)[NG][CU], int c) {
#pragma unroll
        for (int cu = 0; cu < CU; cu++) {
            int k4 = c * CU + cu;
#pragma unroll
            for (int g = 0; g < G; g++) {
                ulonglong2 av = *(const ulonglong2*)(act + g * astride + 4 * k4);
#pragma unroll
                for (int ng = 0; ng < NG; ng++) {
                    acc[ng][g] = ffma2(av.x, w[ng][cu].x, acc[ng][g]);
                    acc[ng][g] = ffma2(av.y, w[ng][cu].y, acc[ng][g]);
                }
            }
        }
    };

    LD(wA, 0);
#pragma unroll 1
    for (int cc = 0; cc < CH / 2; cc++) {
        LD(wB, 2 * cc + 1);
        CP(wA, 2 * cc);
        if (cc + 1 < CH / 2) LD(wA, 2 * cc + 2);
        CP(wB, 2 * cc + 1);
    }

#pragma unroll
    for (int ng = 0; ng < NG; ng++)
#pragma unroll
        for (int g = 0; g < G; g++) res[ng][g] = lanesum(acc[ng][g]);
}

// Accumulating variant: adds into res (for post-wait peer halves).
template <int K2H, int NG, int N, int CU>
__device__ __forceinline__ void gemv_part_acc(
    float (&res)[NG][G],
    const ulonglong2* const (&Wv)[NG],
    const float* act, int astride, int j)
{
    float p[NG][G];
    gemv_part<K2H, NG, N, CU>(p, Wv, act, astride, j);
#pragma unroll
    for (int ng = 0; ng < NG; ng++)
#pragma unroll
        for (int g = 0; g < G; g++) res[ng][g] += p[ng][g];
}

// Per-matrix-activation variant (gate layer 2), CU=1.
template <int K2H, int NG, int N>
__device__ __forceinline__ void gemv_part_ma(
    float (&res)[NG][G],
    const ulonglong2* const (&Wv)[NG],
    const float* const (&av)[NG], int astride, int j)
{
    constexpr int CH = K2H / 2;
    static_assert(CH % 2 == 0, "chunks must be even");

    u64 acc[NG][G];
#pragma unroll
    for (int ng = 0; ng < NG; ng++)
#pragma unroll
        for (int g = 0; g < G; g++) acc[ng][g] = 0ull;

    ulonglong2 wA[NG], wB[NG];

    auto LD = [&](ulonglong2 (&w)[NG], int c) {
#pragma unroll
        for (int ng = 0; ng < NG; ng++) w[ng] = Wv[ng][c * N + j];
    };
    auto CP = [&](ulonglong2 (&w)[NG], int c) {
#pragma unroll
        for (int ng = 0; ng < NG; ng++) {
#pragma unroll
            for (int g = 0; g < G; g++) {
                ulonglong2 avv = *(const ulonglong2*)(av[ng] + g * astride + 4 * c);
                acc[ng][g] = ffma2(avv.x, w[ng].x, acc[ng][g]);
                acc[ng][g] = ffma2(avv.y, w[ng].y, acc[ng][g]);
            }
        }
    };

    LD(wA, 0);
#pragma unroll 1
    for (int cc = 0; cc < CH / 2; cc++) {
        LD(wB, 2 * cc + 1);
        CP(wA, 2 * cc);
        if (cc + 1 < CH / 2) LD(wA, 2 * cc + 2);
        CP(wB, 2 * cc + 1);
    }

#pragma unroll
    for (int ng = 0; ng < NG; ng++)
#pragma unroll
        for (int g = 0; g < G; g++) res[ng][g] = lanesum(acc[ng][g]);
}

template <int K2H, int NG, int N>
__device__ __forceinline__ void gemv_part_ma_acc(
    float (&res)[NG][G],
    const ulonglong2* const (&Wv)[NG],
    const float* const (&av)[NG], int astride, int j)
{
    float p[NG][G];
    gemv_part_ma<K2H, NG, N>(p, Wv, av, astride, j);
#pragma unroll
    for (int ng = 0; ng < NG; ng++)
#pragma unroll
        for (int g = 0; g < G; g++) res[ng][g] += p[ng][g];
}

// Decoder: one (output jd, trajectory) pair, half-K (32 k4 rows), N=128.
__device__ __forceinline__ float gemv_dec1(
    const ulonglong2* W, const float* act, int jd)
{
    constexpr int CU = 4, CH = 8;  // 32 k4 rows
    u64 acc = 0ull;
    ulonglong2 wA[CU], wB[CU];

    auto LD = [&](ulonglong2 (&w)[CU], int c) {
#pragma unroll
        for (int cu = 0; cu < CU; cu++) w[cu] = W[(c * CU + cu) * 128 + jd];
    };
    auto CP = [&](ulonglong2 (&w)[CU], int c) {
#pragma unroll
        for (int cu = 0; cu < CU; cu++) {
            int k4 = c * CU + cu;
            ulonglong2 a = *(const ulonglong2*)(act + 4 * k4);
            acc = ffma2(a.x, w[cu].x, acc);
            acc = ffma2(a.y, w[cu].y, acc);
        }
    };

    LD(wA, 0);
#pragma unroll 1
    for (int cc = 0; cc < CH / 2; cc++) {
        LD(wB, 2 * cc + 1);
        CP(wA, 2 * cc);
        if (cc + 1 < CH / 2) LD(wA, 2 * cc + 2);
        CP(wB, 2 * cc + 1);
    }
    return lanesum(acc);
}

// ---------------------------------------------------------------------------
// Shared memory layout (dynamic). ~95 KB
// ---------------------------------------------------------------------------
struct __align__(16) SM {
    float sy  [G * 256];        // full in both CTAs
    float syt [G * 256];        // full in both CTAs
    float syc [G * GIN];        // full in both CTAs
    float shh0[G * 256];
    float shh1[G * 256];
    float shh2[G * 256];
    float smean[G * 256];       // mean_ydec (local, replicated)
    float Q[3][3][128][G];      // intra-CTA K-quarter partials (kq 0..2 write)
    float Qx[4][4][128][G];     // xh pre-partials [matrix][kq] (all kq write)
    float Pd[64][G];            // decoder kh1 partial
    float Dl[G], Dr[G];         // decay-L2 half sums (local / from peer)
    float sdt[G], smask[G], se1[G], se2[G];
    float sred[4][G];
};
#define SMEM_BYTES ((int)sizeof(SM))

__global__ void __cluster_dims__(2, 1, 1) __launch_bounds__(THREADS, 1)
rnn_decay_kernel(
    const float* __restrict__ data, const float* __restrict__ ts,
    const float* __restrict__ ug_b1,  const float* __restrict__ ug_b2,
    const float* __restrict__ ugt_b1, const float* __restrict__ ugt_b2,
    const float* __restrict__ rg_b1,  const float* __restrict__ rg_b2,
    const float* __restrict__ ns_b1,  const float* __restrict__ ns_b2,
    const float* __restrict__ dk_b1,  const float* __restrict__ dk_w2,
    const float* __restrict__ dk_b2,  const float* __restrict__ dec_b,
    float* __restrict__ out)
{
    extern __shared__ __align__(16) char smraw[];
    SM* sm = reinterpret_cast<SM*>(smraw);

    const int tid  = threadIdx.x;        // 0..511
    const int jloc = tid & 127;          // output column within this CTA's half
    const int kq   = tid >> 7;           // K-quarter 0..3
    const int lane = tid & 31, warp = tid >> 5;
    const uint32_t rank = ctarank();     // N-half owned by this CTA
    const int tb   = (blockIdx.x >> 1) * G;
    const int jglob = (int)rank * 128 + jloc;

    const uint32_t sb = smem_u32(sm);
    const uint32_t pb = mapa_u32(sb, rank ^ 1u);
    const uint32_t pSy   = pb + (uint32_t)offsetof(SM, sy);
    const uint32_t pSyt  = pb + (uint32_t)offsetof(SM, syt);
    const uint32_t pSyc  = pb + (uint32_t)offsetof(SM, syc);
    const uint32_t pShh0 = pb + (uint32_t)offsetof(SM, shh0);
    const uint32_t pShh1 = pb + (uint32_t)offsetof(SM, shh1);
    const uint32_t pShh2 = pb + (uint32_t)offsetof(SM, shh2);
    const uint32_t pDr   = pb + (uint32_t)offsetof(SM, Dr);

    const ulonglong2* WP = g_wp;

    // K-quarter offsets
    const int r256q = kq * 16 * 256;     // 256-row matrices: 16 k4/quarter
    const int a256q = kq * 64;
    const int rxh   = (64 + kq * 8) * 256;  // xh rows of 384-row matrices
    const int axh   = LATENT + kq * 32;     // xh act offset in syc
    // own/peer half-split for dependent gemvs (8 k4 each per kq)
    const int rOwn  = ((int)rank * 32 + kq * 8) * 256;
    const int rPeer = ((int)(rank ^ 1u) * 32 + kq * 8) * 256;
    const int aOwn  = (int)rank * 128 + kq * 32;
    const int aPeer = (int)(rank ^ 1u) * 128 + kq * 32;

    // decoder mapping
    const int jd = tid & 63, gd = (tid >> 6) & 3, kh = tid >> 8;
    const int jdglob = (int)rank * 64 + jd;

    float* out_prev = out;
    float* out_vol  = out + (size_t)NTRAJ * LATENT;
    float* out_dts  = out + (size_t)NTRAJ * LATENT + (size_t)NTRAJ * NSTEP * DEC_OUT;

    for (int i = tid; i < G * 256; i += THREADS) { sm->sy[i] = 0.f; sm->syt[i] = 0.f; }

    CLUSTER_ARRIVE();   // prime: pairs with first loop-top WAIT

    for (int t = 0; t < NTP; t++) {
        __syncthreads();   // all local reads of smask/sdt/syc-tail/Qx from t-1 done

        // ---- setup: xh -> syc tail (full), mask, dt (peer-independent) ----
        {
            int g = tid >> 7, jj = tid & 127;
            sm->syc[g * GIN + LATENT + jj] =
                data[((size_t)(tb + g) * NTP + t) * (2 * INPUT) + jj];
        }
        if (warp < G) {
            const float* xp = data + ((size_t)(tb + warp) * NTP + t) * (2 * INPUT) + INPUT;
            float s = xp[lane] + xp[lane + 32] + xp[lane + 64] + xp[lane + 96];
#pragma unroll
            for (int off = 16; off; off >>= 1) s += __shfl_xor_sync(0xffffffffu, s, off);
            if (lane == 0) sm->smask[warp] = (s > 0.f) ? 1.f : 0.f;
        }
        if (tid < G && t > 0) {
            float d = ts[(size_t)(tb + tid) * NTP + t] - ts[(size_t)(tb + tid) * NTP + t - 1];
            sm->sdt[tid] = d;
            if (rank == 0)
                out_dts[(size_t)(tb + tid) * NSTEP + (t - 1)] = d;
        }
        __syncthreads();

        float u[G], ut[G];   // live in kq3 threads after gate2 combine
        float pdec = 0.f;

        // ---- xh pre-partials (peer-independent; overlaps S0 wait) ----
        {
            const ulonglong2* Wx[4] = { WP + OFF_UG1  + rxh, WP + OFF_UGT1 + rxh,
                                        WP + OFF_RG1  + rxh, WP + OFF_NS1  + rxh };
            float px[4][G];
            gemv_part<16, 4, 256, 1>(px, Wx, sm->syc + axh, GIN, jglob);
#pragma unroll
            for (int m = 0; m < 4; m++)
                *(float4*)&sm->Qx[m][kq][jloc][0] =
                    make_float4(px[m][0], px[m][1], px[m][2], px[m][3]);
        }

        CLUSTER_WAIT();    // S0: peer sy/syt state arrives

        if (t > 0) {
            // ---- decay layer1 (own N-half, full K via kq quarters) ----
            {
                const ulonglong2* Wd[1] = { WP + OFF_DK1 + r256q };
                float p[1][G];
                gemv_part<32, 1, 256, 4>(p, Wd, sm->sy + a256q, 256, jglob);
                if (kq != 3)
                    *(float4*)&sm->Q[0][kq][jloc][0] =
                        make_float4(p[0][0], p[0][1], p[0][2], p[0][3]);
                __syncthreads();
                if (kq == 3) {
                    float bv = dk_b1[jglob];
                    float w2v = dk_w2[jglob];
                    float4 q0 = *(const float4*)&sm->Q[0][0][jloc][0];
                    float4 q1 = *(const float4*)&sm->Q[0][1][jloc][0];
                    float4 q2 = *(const float4*)&sm->Q[0][2][jloc][0];
                    float v[G];
                    v[0] = fmaxf(p[0][0] + q0.x + q1.x + q2.x + bv, 0.f) * w2v;
                    v[1] = fmaxf(p[0][1] + q0.y + q1.y + q2.y + bv, 0.f) * w2v;
                    v[2] = fmaxf(p[0][2] + q0.z + q1.z + q2.z + bv, 0.f) * w2v;
                    v[3] = fmaxf(p[0][3] + q0.w + q1.w + q2.w + bv, 0.f) * w2v;
#pragma unroll
                    for (int off = 16; off; off >>= 1)
#pragma unroll
                        for (int g = 0; g < G; g++)
                            v[g] += __shfl_xor_sync(0xffffffffu, v[g], off);
                    if (lane == 0)
#pragma unroll
                        for (int g = 0; g < G; g++) sm->sred[warp & 3][g] = v[g];
                }
                __syncthreads();
                if (tid < G) {
                    float s = sm->sred[0][tid] + sm->sred[1][tid]
                            + sm->sred[2][tid] + sm->sred[3][tid];
                    sm->Dl[tid] = s;
                    st_peer_f1(pDr + (uint32_t)tid * 4u, s);
                }
            }
            CLUSTER_SYNC();  // CS1
            if (tid < G) {
                float dec = fmaxf(sm->Dl[tid] + sm->Dr[tid] + dk_b2[0], 0.f);
                float d = dec * sm->sdt[tid];
                sm->se1[tid] = __expf(-0.5f * d);
                sm->se2[tid] = __expf(-d);
            }
            __syncthreads();

            // ---- elementwise decay (replicated in both CTAs) ----
            for (int it = tid; it < G * 256; it += THREADS) {
                int g = it >> 8, jj = it & 255;
                float yv = sm->sy[g * 256 + jj], ytv = sm->syt[g * 256 + jj];
                float df = yv - ytv;
                sm->smean[g * 256 + jj] = ytv + df * (0.5f * (1.f + sm->se1[g]));
                float ye = ytv + df * sm->se2[g];
                sm->sy[g * 256 + jj] = ye;
                sm->syc[g * GIN + jj] = ye;
            }
            __syncthreads();

            // ---- decoder partial (own 64 columns, half-K per kh) ----
            {
                const ulonglong2* Wd = WP + OFF_DEC + kh * 32 * 128;
                pdec = gemv_dec1(Wd, sm->smean + gd * 256 + kh * 128, jdglob);
                if (kh) sm->Pd[jd][gd] = pdec;
            }
        } else {
            for (int it = tid; it < G * 256; it += THREADS) {
                int g = it >> 8, jj = it & 255;
                sm->syc[g * GIN + jj] = 0.f;
            }
            __syncthreads();
        }

        // ---- gate layer1: ug/ugt/rg y-part (256->own 128 cols) ----
        {
            const ulonglong2* Wg[3] = { WP + OFF_UG1  + r256q,
                                        WP + OFF_UGT1 + r256q,
                                        WP + OFF_RG1  + r256q };
            float p[3][G];
            gemv_part<32, 3, 256, 2>(p, Wg, sm->syc + a256q, GIN, jglob);
            if (kq != 3) {
#pragma unroll
                for (int m = 0; m < 3; m++)
                    *(float4*)&sm->Q[m][kq][jloc][0] =
                        make_float4(p[m][0], p[m][1], p[m][2], p[m][3]);
            }
            __syncthreads();   // also publishes Pd
            if (kq == 3) {
                const float* B1[3] = { ug_b1, ugt_b1, rg_b1 };
                float* SH[3] = { sm->shh0, sm->shh1, sm->shh2 };
                const uint32_t PSH[3] = { pShh0, pShh1, pShh2 };
#pragma unroll
                for (int m = 0; m < 3; m++) {
                    float bv = B1[m][jglob];
                    float4 q0 = *(const float4*)&sm->Q[m][0][jloc][0];
                    float4 q1 = *(const float4*)&sm->Q[m][1][jloc][0];
                    float4 q2 = *(const float4*)&sm->Q[m][2][jloc][0];
                    float4 x0 = *(const float4*)&sm->Qx[m][0][jloc][0];
                    float4 x1 = *(const float4*)&sm->Qx[m][1][jloc][0];
                    float4 x2 = *(const float4*)&sm->Qx[m][2][jloc][0];
                    float4 x3 = *(const float4*)&sm->Qx[m][3][jloc][0];
                    float vv[G] = {
                        p[m][0] + q0.x + q1.x + q2.x + x0.x + x1.x + x2.x + x3.x + bv,
                        p[m][1] + q0.y + q1.y + q2.y + x0.y + x1.y + x2.y + x3.y + bv,
                        p[m][2] + q0.z + q1.z + q2.z + x0.z + x1.z + x2.z + x3.z + bv,
                        p[m][3] + q0.w + q1.w + q2.w + x0.w + x1.w + x2.w + x3.w + bv };
#pragma unroll
                    for (int g = 0; g < G; g++) {
                        float a = tanhf(vv[g]);
                        int idx = g * 256 + jglob;
                        SH[m][idx] = a;
                        st_peer_f1(PSH[m] + (uint32_t)idx * 4u, a);
                    }
                }
            } else if (t > 0 && kh == 0) {
                // decoder finalize -> global (own 64 columns)
                float v = pdec + sm->Pd[jd][gd] + dec_b[jdglob];
                out_vol[((size_t)(tb + gd) * NSTEP + (t - 1)) * DEC_OUT + jdglob] = v;
            }
            pf_l1(WP + OFF_UG2  + rOwn + jglob);
            pf_l1(WP + OFF_UGT2 + rOwn + jglob);
            pf_l1(WP + OFF_RG2  + rOwn + jglob);
        }
        __syncthreads();       // publish local shh (own half) for own-part gemv
        CLUSTER_ARRIVE();      // CS2 arrive (peer-stores of shh released)

        // ---- gate layer2 x3: own-half K before wait, peer-half after ----
        {
            float p[3][G];
            {
                const ulonglong2* Wg[3] = { WP + OFF_UG2  + rOwn,
                                            WP + OFF_UGT2 + rOwn,
                                            WP + OFF_RG2  + rOwn };
                const float* av[3] = { sm->shh0 + aOwn, sm->shh1 + aOwn,
                                       sm->shh2 + aOwn };
                gemv_part_ma<16, 3, 256>(p, Wg, av, 256, jglob);
            }
            CLUSTER_WAIT();    // CS2 wait: peer shh halves arrive
            {
                const ulonglong2* Wg[3] = { WP + OFF_UG2  + rPeer,
                                            WP + OFF_UGT2 + rPeer,
                                            WP + OFF_RG2  + rPeer };
                const float* av[3] = { sm->shh0 + aPeer, sm->shh1 + aPeer,
                                       sm->shh2 + aPeer };
                gemv_part_ma_acc<16, 3, 256>(p, Wg, av, 256, jglob);
            }
            if (kq != 3) {
#pragma unroll
                for (int m = 0; m < 3; m++)
                    *(float4*)&sm->Q[m][kq][jloc][0] =
                        make_float4(p[m][0], p[m][1], p[m][2], p[m][3]);
            }
            __syncthreads();
            if (kq == 3) {
                float b0 = ug_b2[jglob], b1 = ugt_b2[jglob], b2 = rg_b2[jglob];
                float4 q0, q1, q2;
                q0 = *(const float4*)&sm->Q[0][0][jloc][0];
                q1 = *(const float4*)&sm->Q[0][1][jloc][0];
                q2 = *(const float4*)&sm->Q[0][2][jloc][0];
                u[0] = sigmoid_fast(p[0][0] + q0.x + q1.x + q2.x + b0);
                u[1] = sigmoid_fast(p[0][1] + q0.y + q1.y + q2.y + b0);
                u[2] = sigmoid_fast(p[0][2] + q0.z + q1.z + q2.z + b0);
                u[3] = sigmoid_fast(p[0][3] + q0.w + q1.w + q2.w + b0);
                q0 = *(const float4*)&sm->Q[1][0][jloc][0];
                q1 = *(const float4*)&sm->Q[1][1][jloc][0];
                q2 = *(const float4*)&sm->Q[1][2][jloc][0];
                ut[0] = sigmoid_fast(p[1][0] + q0.x + q1.x + q2.x + b1);
                ut[1] = sigmoid_fast(p[1][1] + q0.y + q1.y + q2.y + b1);
                ut[2] = sigmoid_fast(p[1][2] + q0.z + q1.z + q2.z + b1);
                ut[3] = sigmoid_fast(p[1][3] + q0.w + q1.w + q2.w + b1);
                q0 = *(const float4*)&sm->Q[2][0][jloc][0];
                q1 = *(const float4*)&sm->Q[2][1][jloc][0];
                q2 = *(const float4*)&sm->Q[2][2][jloc][0];
                float rr[G] = { sigmoid_fast(p[2][0] + q0.x + q1.x + q2.x + b2),
                                sigmoid_fast(p[2][1] + q0.y + q1.y + q2.y + b2),
                                sigmoid_fast(p[2][2] + q0.z + q1.z + q2.z + b2),
                                sigmoid_fast(p[2][3] + q0.w + q1.w + q2.w + b2) };
#pragma unroll
                for (int g = 0; g < G; g++) {
                    int idx = g * GIN + jglob;
                    float v = sm->syc[idx] * rr[g];
                    sm->syc[idx] = v;
                    st_peer_f1(pSyc + (uint32_t)idx * 4u, v);
                }
            }
            pf_l1(WP + OFF_NS1 + rOwn + jglob);
        }
        __syncthreads();       // publish local syc head (own half)
        CLUSTER_ARRIVE();      // CS3 arrive

        // ---- new_state layer1: own-half y before wait, peer after; +xh ----
        {
            float p[1][G];
            {
                const ulonglong2* Wg[1] = { WP + OFF_NS1 + rOwn };
                gemv_part<16, 1, 256, 2>(p, Wg, sm->syc + aOwn, GIN, jglob);
            }
            CLUSTER_WAIT();    // CS3 wait: peer syc head arrives
            {
                const ulonglong2* Wg[1] = { WP + OFF_NS1 + rPeer };
                gemv_part_acc<16, 1, 256, 2>(p, Wg, sm->syc + aPeer, GIN, jglob);
            }
            if (kq != 3)
                *(float4*)&sm->Q[0][kq][jloc][0] =
                    make_float4(p[0][0], p[0][1], p[0][2], p[0][3]);
            __syncthreads();
            if (kq == 3) {
                float bv = ns_b1[jglob];
                float4 q0 = *(const float4*)&sm->Q[0][0][jloc][0];
                float4 q1 = *(const float4*)&sm->Q[0][1][jloc][0];
                float4 q2 = *(const float4*)&sm->Q[0][2][jloc][0];
                float4 x0 = *(const float4*)&sm->Qx[3][0][jloc][0];
                float4 x1 = *(const float4*)&sm->Qx[3][1][jloc][0];
                float4 x2 = *(const float4*)&sm->Qx[3][2][jloc][0];
                float4 x3 = *(const float4*)&sm->Qx[3][3][jloc][0];
                float vv[G] = {
                    p[0][0] + q0.x + q1.x + q2.x + x0.x + x1.x + x2.x + x3.x + bv,
                    p[0][1] + q0.y + q1.y + q2.y + x0.y + x1.y + x2.y + x3.y + bv,
                    p[0][2] + q0.z + q1.z + q2.z + x0.z + x1.z + x2.z + x3.z + bv,
                    p[0][3] + q0.w + q1.w + q2.w + x0.w + x1.w + x2.w + x3.w + bv };
#pragma unroll
                for (int g = 0; g < G; g++) {
                    float a = tanhf(vv[g]);
                    int idx = g * 256 + jglob;
                    sm->shh0[idx] = a;
                    st_peer_f1(pShh0 + (uint32_t)idx * 4u, a);
                }
            }
            pf_l1(WP + OFF_NS2 + rOwn + jglob);
        }
        __syncthreads();       // publish local shh0 (own half)
        CLUSTER_ARRIVE();      // CS4 arrive

        // ---- new_state layer2: own-half before wait, peer after; update ----
        {
            float p[1][G];
            {
                const ulonglong2* Wg[1] = { WP + OFF_NS2 + rOwn };
                gemv_part<16, 1, 256, 2>(p, Wg, sm->shh0 + aOwn, 256, jglob);
            }
            CLUSTER_WAIT();    // CS4 wait
            {
                const ulonglong2* Wg[1] = { WP + OFF_NS2 + rPeer };
                gemv_part_acc<16, 1, 256, 2>(p, Wg, sm->shh0 + aPeer, 256, jglob);
            }
            if (kq != 3)
                *(float4*)&sm->Q[0][kq][jloc][0] =
                    make_float4(p[0][0], p[0][1], p[0][2], p[0][3]);
            __syncthreads();
            if (kq == 3) {
                float bv = ns_b2[jglob];
                float4 q0 = *(const float4*)&sm->Q[0][0][jloc][0];
                float4 q1 = *(const float4*)&sm->Q[0][1][jloc][0];
                float4 q2 = *(const float4*)&sm->Q[0][2][jloc][0];
                float nsv[G] = { p[0][0] + q0.x + q1.x + q2.x + bv,
                                 p[0][1] + q0.y + q1.y + q2.y + bv,
                                 p[0][2] + q0.z + q1.z + q2.z + bv,
                                 p[0][3] + q0.w + q1.w + q2.w + bv };
#pragma unroll
                for (int g = 0; g < G; g++) {
                    float m    = sm->smask[g];
                    int idx    = g * 256 + jglob;
                    float yend = sm->sy[idx], ytv = sm->syt[idx];
                    float ny   = (1.f - u[g])  * nsv[g] + u[g]  * yend;
                    float nyt  = (1.f - ut[g]) * nsv[g] + ut[g] * ytv;
                    float oy   = m * ny  + (1.f - m) * yend;
                    float oyt  = m * nyt + (1.f - m) * ytv;
                    sm->sy[idx]  = oy;
                    sm->syt[idx] = oyt;
                    st_peer_f1(pSy  + (uint32_t)idx * 4u, oy);
                    st_peer_f1(pSyt + (uint32_t)idx * 4u, oyt);
                }
            }
        }
        CLUSTER_ARRIVE();      // S0 arrive for next step (state released)
    }

    CLUSTER_WAIT();            // final pairing
    if (rank == 0 && tid < 256) {
#pragma unroll
        for (int g = 0; g < G; g++)
            out_prev[(size_t)(tb + g) * LATENT + tid] = sm->sy[g * 256 + tid];
    }
}

extern "C" void kernel_launch(void* const* d_in, const int* in_sizes, int n_in,
                              void* d_out, int out_size) {
    const float* data   = (const float*)d_in[0];
    const float* ts     = (const float*)d_in[1];
    const float* ug_w1  = (const float*)d_in[2];
    const float* ug_b1  = (const float*)d_in[3];
    const float* ug_w2  = (const float*)d_in[4];
    const float* ug_b2  = (const float*)d_in[5];
    const float* ugt_w1 = (const float*)d_in[6];
    const float* ugt_b1 = (const float*)d_in[7];
    const float* ugt_w2 = (const float*)d_in[8];
    const float* ugt_b2 = (const float*)d_in[9];
    const float* rg_w1  = (const float*)d_in[10];
    const float* rg_b1  = (const float*)d_in[11];
    const float* rg_w2  = (const float*)d_in[12];
    const float* rg_b2  = (const float*)d_in[13];
    // d_in[14..17] = rgt_* : unused by the reference
    const float* ns_w1  = (const float*)d_in[18];
    const float* ns_b1  = (const float*)d_in[19];
    const float* ns_w2  = (const float*)d_in[20];
    const float* ns_b2  = (const float*)d_in[21];
    const float* dk_w1  = (const float*)d_in[22];
    const float* dk_b1  = (const float*)d_in[23];
    const float* dk_w2  = (const float*)d_in[24];
    const float* dk_b2  = (const float*)d_in[25];
    const float* dec_w  = (const float*)d_in[26];
    const float* dec_b  = (const float*)d_in[27];

    cudaFuncSetAttribute(rnn_decay_kernel,
                         cudaFuncAttributeMaxDynamicSharedMemorySize, SMEM_BYTES);

    pack_kernel<<<(WP_TOTAL + 255) / 256, 256>>>(
        ug_w1, ugt_w1, rg_w1, ns_w1, ug_w2, ugt_w2, rg_w2, ns_w2, dk_w1, dec_w);

    rnn_decay_kernel<<<NBLK, THREADS, SMEM_BYTES>>>(
        data, ts,
        ug_b1, ug_b2, ugt_b1, ugt_b2, rg_b1, rg_b2,
        ns_b1, ns_b2, dk_b1, dk_w2, dk_b2, dec_b,
        (float*)d_out);
}

// round 17
// speedup vs baseline: 1.1085x; 1.0317x over previous
#include <cuda_runtime.h>
#include <cuda_bf16.h>
#include <cuda_fp16.h>
#include <math.h>
#include <stdint.h>
#include <stddef.h>

#define NTRAJ  256
#define NTP    512
#define LATENT 256
#define INPUT  128
#define NUNITS 256
#define GIN    (LATENT + INPUT)   // 384
#define DEC_OUT 128
#define NSTEP  (NTP - 1)          // 511

#define G       4                 // trajectories per cluster
#define NCLU    (NTRAJ / G)       // 64 clusters
#define NBLK    (NCLU * 2)        // 128 CTAs (2 per cluster, N-split)
#define THREADS 512               // intra-CTA split-K x4 (kq groups)

typedef unsigned long long u64;

union F2U { float2 f; u64 u; };

__device__ __forceinline__ u64 ffma2(u64 a, u64 b, u64 c) {
    u64 d;
    asm("fma.rn.f32x2 %0, %1, %2, %3;" : "=l"(d) : "l"(a), "l"(b), "l"(c));
    return d;
}
__device__ __forceinline__ float lanesum(u64 v) {
    F2U r; r.u = v; return r.f.x + r.f.y;
}
__device__ __forceinline__ float sigmoid_fast(float x) {
    return __fdividef(1.f, 1.f + __expf(-x));
}
__device__ __forceinline__ uint32_t smem_u32(const void* p) {
    uint32_t a;
    asm("{ .reg .u64 t; cvta.to.shared.u64 t, %1; cvt.u32.u64 %0, t; }" : "=r"(a) : "l"(p));
    return a;
}
__device__ __forceinline__ uint32_t ctarank() {
    uint32_t r; asm("mov.u32 %0, %%cluster_ctarank;" : "=r"(r)); return r;
}
__device__ __forceinline__ uint32_t mapa_u32(uint32_t addr, uint32_t rank) {
    uint32_t r;
    asm("mapa.shared::cluster.u32 %0, %1, %2;" : "=r"(r) : "r"(addr), "r"(rank));
    return r;
}
__device__ __forceinline__ void st_peer_f1(uint32_t dst, float v) {
    asm volatile("st.shared::cluster.u32 [%0], %1;" :: "r"(dst), "f"(v) : "memory");
}
__device__ __forceinline__ void pf_l1(const void* p) {
    asm volatile("prefetch.global.L1 [%0];" :: "l"(p));
}
#define CLUSTER_ARRIVE() asm volatile("barrier.cluster.arrive.aligned;" ::: "memory")
#define CLUSTER_WAIT()   asm volatile("barrier.cluster.wait.aligned;"   ::: "memory")
#define CLUSTER_SYNC() do { CLUSTER_ARRIVE(); CLUSTER_WAIT(); } while (0)

// expand 8 fp16 weights (one ulonglong2) into 4 packed-f32x2 u64s
__device__ __forceinline__ void expand8(ulonglong2 w, u64 (&e)[4]) {
    uint32_t h0 = (uint32_t)w.x, h1 = (uint32_t)(w.x >> 32);
    uint32_t h2 = (uint32_t)w.y, h3 = (uint32_t)(w.y >> 32);
    F2U t;
    t.f = __half22float2(*reinterpret_cast<const __half2*>(&h0)); e[0] = t.u;
    t.f = __half22float2(*reinterpret_cast<const __half2*>(&h1)); e[1] = t.u;
    t.f = __half22float2(*reinterpret_cast<const __half2*>(&h2)); e[2] = t.u;
    t.f = __half22float2(*reinterpret_cast<const __half2*>(&h3)); e[3] = t.u;
}

// ---------------------------------------------------------------------------
// Packed fp16 weights: 8 along k per ulonglong2: W8[k8][j] = W[8k8..8k8+7][j].
// ---------------------------------------------------------------------------
#define SZ_M384 (48 * 256)
#define SZ_M256 (32 * 256)
#define SZ_DEC  (32 * 128)
#define OFF_UG1  0
#define OFF_UGT1 (OFF_UG1  + SZ_M384)
#define OFF_RG1  (OFF_UGT1 + SZ_M384)
#define OFF_NS1  (OFF_RG1  + SZ_M384)
#define OFF_UG2  (OFF_NS1  + SZ_M384)
#define OFF_UGT2 (OFF_UG2  + SZ_M256)
#define OFF_RG2  (OFF_UGT2 + SZ_M256)
#define OFF_NS2  (OFF_RG2  + SZ_M256)
#define OFF_DK1  (OFF_NS2  + SZ_M256)
#define OFF_DEC  (OFF_DK1  + SZ_M256)
#define WP_TOTAL (OFF_DEC  + SZ_DEC)

__device__ ulonglong2 g_wp[WP_TOTAL];

__global__ void pack_kernel(
    const float* ug1, const float* ugt1, const float* rg1, const float* ns1,
    const float* ug2, const float* ugt2, const float* rg2, const float* ns2,
    const float* dk1, const float* decw)
{
    const float* srcs[10] = {ug1, ugt1, rg1, ns1, ug2, ugt2, rg2, ns2, dk1, decw};
    const int offs[11] = {OFF_UG1, OFF_UGT1, OFF_RG1, OFF_NS1, OFF_UG2, OFF_UGT2,
                          OFF_RG2, OFF_NS2, OFF_DK1, OFF_DEC, WP_TOTAL};
    const int Ns[10] = {256,256,256,256,256,256,256,256,256,128};

    int idx = blockIdx.x * blockDim.x + threadIdx.x;
    if (idx >= WP_TOTAL) return;
    int m = 0;
    while (idx >= offs[m + 1]) m++;
    int local = idx - offs[m];
    int N = Ns[m];
    int k8 = local / N, j = local % N;
    const float* S = srcs[m];
    uint64_t x = 0, y = 0;
#pragma unroll
    for (int i = 0; i < 4; i++) {
        uint16_t b = __half_as_ushort(__float2half_rn(S[(8 * k8 + i) * N + j]));
        x |= (uint64_t)b << (16 * i);
    }
#pragma unroll
    for (int i = 0; i < 4; i++) {
        uint16_t b = __half_as_ushort(__float2half_rn(S[(8 * k8 + 4 + i) * N + j]));
        y |= (uint64_t)b << (16 * i);
    }
    g_wp[idx] = make_ulonglong2(x, y);
}

// ---------------------------------------------------------------------------
// Partial packed GEMV (K8 rows of 8 weights), shared activation.
// ---------------------------------------------------------------------------
template <int K8, int NG, int N, int CU>
__device__ __forceinline__ void gemv_part(
    float (&res)[NG][G],
    const ulonglong2* const (&Wv)[NG],
    const float* act, int astride, int j)
{
    constexpr int CH = K8 / CU;
    static_assert(CH % 2 == 0, "chunks must be even");

    u64 acc[NG][G];
#pragma unroll
    for (int ng = 0; ng < NG; ng++)
#pragma unroll
        for (int g = 0; g < G; g++) acc[ng][g] = 0ull;

    ulonglong2 wA[NG][CU], wB[NG][CU];

    auto LD = [&](ulonglong2 (&w)[NG][CU], int c) {
#pragma unroll
        for (int ng = 0; ng < NG; ng++)
#pragma unroll
            for (int cu = 0; cu < CU; cu++)
                w[ng][cu] = Wv[ng][(c * CU + cu) * N + j];
    };
    auto CP = [&](ulonglong2 (&w)[NG][CU], int c) {
#pragma unroll
        for (int cu = 0; cu < CU; cu++) {
            int k8 = c * CU + cu;
            u64 e[NG][4];
#pragma unroll
            for (int ng = 0; ng < NG; ng++) expand8(w[ng][cu], e[ng]);
#pragma unroll
            for (int g = 0; g < G; g++) {
                ulonglong2 a0 = *(const ulonglong2*)(act + g * astride + 8 * k8);
                ulonglong2 a1 = *(const ulonglong2*)(act + g * astride + 8 * k8 + 4);
#pragma unroll
                for (int ng = 0; ng < NG; ng++) {
                    acc[ng][g] = ffma2(a0.x, e[ng][0], acc[ng][g]);
                    acc[ng][g] = ffma2(a0.y, e[ng][1], acc[ng][g]);
                    acc[ng][g] = ffma2(a1.x, e[ng][2], acc[ng][g]);
                    acc[ng][g] = ffma2(a1.y, e[ng][3], acc[ng][g]);
                }
            }
        }
    };

    LD(wA, 0);
#pragma unroll 1
    for (int cc = 0; cc < CH / 2; cc++) {
        LD(wB, 2 * cc + 1);
        CP(wA, 2 * cc);
        if (cc + 1 < CH / 2) LD(wA, 2 * cc + 2);
        CP(wB, 2 * cc + 1);
    }

#pragma unroll
    for (int ng = 0; ng < NG; ng++)
#pragma unroll
        for (int g = 0; g < G; g++) res[ng][g] = lanesum(acc[ng][g]);
}

template <int K8, int NG, int N, int CU>
__device__ __forceinline__ void gemv_part_acc(
    float (&res)[NG][G],
    const ulonglong2* const (&Wv)[NG],
    const float* act, int astride, int j)
{
    float p[NG][G];
    gemv_part<K8, NG, N, CU>(p, Wv, act, astride, j);
#pragma unroll
    for (int ng = 0; ng < NG; ng++)
#pragma unroll
        for (int g = 0; g < G; g++) res[ng][g] += p[ng][g];
}

// Per-matrix-activation variant (gate layer 2), CU=1.
template <int K8, int NG, int N>
__device__ __forceinline__ void gemv_part_ma(
    float (&res)[NG][G],
    const ulonglong2* const (&Wv)[NG],
    const float* const (&av)[NG], int astride, int j)
{
    constexpr int CH = K8;
    static_assert(CH % 2 == 0, "chunks must be even");

    u64 acc[NG][G];
#pragma unroll
    for (int ng = 0; ng < NG; ng++)
#pragma unroll
        for (int g = 0; g < G; g++) acc[ng][g] = 0ull;

    ulonglong2 wA[NG], wB[NG];

    auto LD = [&](ulonglong2 (&w)[NG], int c) {
#pragma unroll
        for (int ng = 0; ng < NG; ng++) w[ng] = Wv[ng][c * N + j];
    };
    auto CP = [&](ulonglong2 (&w)[NG], int c) {
        u64 e[NG][4];
#pragma unroll
        for (int ng = 0; ng < NG; ng++) expand8(w[ng], e[ng]);
#pragma unroll
        for (int ng = 0; ng < NG; ng++) {
#pragma unroll
            for (int g = 0; g < G; g++) {
                ulonglong2 a0 = *(const ulonglong2*)(av[ng] + g * astride + 8 * c);
                ulonglong2 a1 = *(const ulonglong2*)(av[ng] + g * astride + 8 * c + 4);
                acc[ng][g] = ffma2(a0.x, e[ng][0], acc[ng][g]);
                acc[ng][g] = ffma2(a0.y, e[ng][1], acc[ng][g]);
                acc[ng][g] = ffma2(a1.x, e[ng][2], acc[ng][g]);
                acc[ng][g] = ffma2(a1.y, e[ng][3], acc[ng][g]);
            }
        }
    };

    LD(wA, 0);
#pragma unroll 1
    for (int cc = 0; cc < CH / 2; cc++) {
        LD(wB, 2 * cc + 1);
        CP(wA, 2 * cc);
        if (cc + 1 < CH / 2) LD(wA, 2 * cc + 2);
        CP(wB, 2 * cc + 1);
    }

#pragma unroll
    for (int ng = 0; ng < NG; ng++)
#pragma unroll
        for (int g = 0; g < G; g++) res[ng][g] = lanesum(acc[ng][g]);
}

template <int K8, int NG, int N>
__device__ __forceinline__ void gemv_part_ma_acc(
    float (&res)[NG][G],
    const ulonglong2* const (&Wv)[NG],
    const float* const (&av)[NG], int astride, int j)
{
    float p[NG][G];
    gemv_part_ma<K8, NG, N>(p, Wv, av, astride, j);
#pragma unroll
    for (int ng = 0; ng < NG; ng++)
#pragma unroll
        for (int g = 0; g < G; g++) res[ng][g] += p[ng][g];
}

// Decoder: one (output jd, trajectory) pair, half-K (16 k8 rows), N=128.
__device__ __forceinline__ float gemv_dec1(
    const ulonglong2* W, const float* act, int jd)
{
    constexpr int CU = 2, CH = 8;  // 16 k8 rows
    u64 acc = 0ull;
    ulonglong2 wA[CU], wB[CU];

    auto LD = [&](ulonglong2 (&w)[CU], int c) {
#pragma unroll
        for (int cu = 0; cu < CU; cu++) w[cu] = W[(c * CU + cu) * 128 + jd];
    };
    auto CP = [&](ulonglong2 (&w)[CU], int c) {
#pragma unroll
        for (int cu = 0; cu < CU; cu++) {
            int k8 = c * CU + cu;
            u64 e[4];
            expand8(w[cu], e);
            ulonglong2 a0 = *(const ulonglong2*)(act + 8 * k8);
            ulonglong2 a1 = *(const ulonglong2*)(act + 8 * k8 + 4);
            acc = ffma2(a0.x, e[0], acc);
            acc = ffma2(a0.y, e[1], acc);
            acc = ffma2(a1.x, e[2], acc);
            acc = ffma2(a1.y, e[3], acc);
        }
    };

    LD(wA, 0);
#pragma unroll 1
    for (int cc = 0; cc < CH / 2; cc++) {
        LD(wB, 2 * cc + 1);
        CP(wA, 2 * cc);
        if (cc + 1 < CH / 2) LD(wA, 2 * cc + 2);
        CP(wB, 2 * cc + 1);
    }
    return lanesum(acc);
}

// ---------------------------------------------------------------------------
// Shared memory layout (dynamic). ~95 KB
// ---------------------------------------------------------------------------
struct __align__(16) SM {
    float sy  [G * 256];        // full in both CTAs
    float syt [G * 256];        // full in both CTAs
    float syc [G * GIN];        // full in both CTAs
    float shh0[G * 256];
    float shh1[G * 256];
    float shh2[G * 256];
    float smean[G * 256];       // mean_ydec (local, replicated)
    float Q[3][3][128][G];      // intra-CTA K-quarter partials (kq 0..2 write)
    float Qx[4][4][128][G];     // xh pre-partials [matrix][kq] (all kq write)
    float Pd[64][G];            // decoder kh1 partial
    float Dl[G], Dr[G];         // decay-L2 half sums (local / from peer)
    float sdt[G], smask[G], se1[G], se2[G];
    float sred[4][G];
};
#define SMEM_BYTES ((int)sizeof(SM))

__global__ void __cluster_dims__(2, 1, 1) __launch_bounds__(THREADS, 1)
rnn_decay_kernel(
    const float* __restrict__ data, const float* __restrict__ ts,
    const float* __restrict__ ug_b1,  const float* __restrict__ ug_b2,
    const float* __restrict__ ugt_b1, const float* __restrict__ ugt_b2,
    const float* __restrict__ rg_b1,  const float* __restrict__ rg_b2,
    const float* __restrict__ ns_b1,  const float* __restrict__ ns_b2,
    const float* __restrict__ dk_b1,  const float* __restrict__ dk_w2,
    const float* __restrict__ dk_b2,  const float* __restrict__ dec_b,
    float* __restrict__ out)
{
    extern __shared__ __align__(16) char smraw[];
    SM* sm = reinterpret_cast<SM*>(smraw);

    const int tid  = threadIdx.x;        // 0..511
    const int jloc = tid & 127;          // output column within this CTA's half
    const int kq   = tid >> 7;           // K-quarter 0..3
    const int lane = tid & 31, warp = tid >> 5;
    const uint32_t rank = ctarank();     // N-half owned by this CTA
    const int tb   = (blockIdx.x >> 1) * G;
    const int jglob = (int)rank * 128 + jloc;

    const uint32_t sb = smem_u32(sm);
    const uint32_t pb = mapa_u32(sb, rank ^ 1u);
    const uint32_t pSy   = pb + (uint32_t)offsetof(SM, sy);
    const uint32_t pSyt  = pb + (uint32_t)offsetof(SM, syt);
    const uint32_t pSyc  = pb + (uint32_t)offsetof(SM, syc);
    const uint32_t pShh0 = pb + (uint32_t)offsetof(SM, shh0);
    const uint32_t pShh1 = pb + (uint32_t)offsetof(SM, shh1);
    const uint32_t pShh2 = pb + (uint32_t)offsetof(SM, shh2);
    const uint32_t pDr   = pb + (uint32_t)offsetof(SM, Dr);

    const ulonglong2* WP = g_wp;

    // K-quarter offsets (k8 units)
    const int r256q = kq * 8 * 256;         // 256-row matrices: 8 k8/quarter
    const int a256q = kq * 64;
    const int rxh   = (32 + kq * 4) * 256;  // xh rows of 384-row matrices
    const int axh   = LATENT + kq * 32;     // xh act offset in syc
    // own/peer half-split for dependent gemvs (4 k8 each per kq)
    const int rOwn  = ((int)rank * 16 + kq * 4) * 256;
    const int rPeer = ((int)(rank ^ 1u) * 16 + kq * 4) * 256;
    const int aOwn  = (int)rank * 128 + kq * 32;
    const int aPeer = (int)(rank ^ 1u) * 128 + kq * 32;

    // decoder mapping
    const int jd = tid & 63, gd = (tid >> 6) & 3, kh = tid >> 8;
    const int jdglob = (int)rank * 64 + jd;

    float* out_prev = out;
    float* out_vol  = out + (size_t)NTRAJ * LATENT;
    float* out_dts  = out + (size_t)NTRAJ * LATENT + (size_t)NTRAJ * NSTEP * DEC_OUT;

    for (int i = tid; i < G * 256; i += THREADS) { sm->sy[i] = 0.f; sm->syt[i] = 0.f; }

    CLUSTER_ARRIVE();   // prime: pairs with first loop-top WAIT

    for (int t = 0; t < NTP; t++) {
        __syncthreads();   // all local reads of smask/sdt/syc-tail/Qx from t-1 done

        // ---- setup: xh -> syc tail (full), mask, dt (peer-independent) ----
        {
            int g = tid >> 7, jj = tid & 127;
            sm->syc[g * GIN + LATENT + jj] =
                data[((size_t)(tb + g) * NTP + t) * (2 * INPUT) + jj];
        }
        if (warp < G) {
            const float* xp = data + ((size_t)(tb + warp) * NTP + t) * (2 * INPUT) + INPUT;
            float s = xp[lane] + xp[lane + 32] + xp[lane + 64] + xp[lane + 96];
#pragma unroll
            for (int off = 16; off; off >>= 1) s += __shfl_xor_sync(0xffffffffu, s, off);
            if (lane == 0) sm->smask[warp] = (s > 0.f) ? 1.f : 0.f;
        }
        if (tid < G && t > 0) {
            float d = ts[(size_t)(tb + tid) * NTP + t] - ts[(size_t)(tb + tid) * NTP + t - 1];
            sm->sdt[tid] = d;
            if (rank == 0)
                out_dts[(size_t)(tb + tid) * NSTEP + (t - 1)] = d;
        }
        __syncthreads();

        float u[G], ut[G];   // live in kq3 threads after gate2 combine
        float pdec = 0.f;

        // ---- xh pre-partials (peer-independent; overlaps S0 wait) ----
        {
            const ulonglong2* Wx[4] = { WP + OFF_UG1  + rxh, WP + OFF_UGT1 + rxh,
                                        WP + OFF_RG1  + rxh, WP + OFF_NS1  + rxh };
            float px[4][G];
            gemv_part<4, 4, 256, 1>(px, Wx, sm->syc + axh, GIN, jglob);
#pragma unroll
            for (int m = 0; m < 4; m++)
                *(float4*)&sm->Qx[m][kq][jloc][0] =
                    make_float4(px[m][0], px[m][1], px[m][2], px[m][3]);
        }

        CLUSTER_WAIT();    // S0: peer sy/syt state arrives

        if (t > 0) {
            // ---- decay layer1 (own N-half, full K via kq quarters) ----
            {
                const ulonglong2* Wd[1] = { WP + OFF_DK1 + r256q };
                float p[1][G];
                gemv_part<8, 1, 256, 2>(p, Wd, sm->sy + a256q, 256, jglob);
                if (kq != 3)
                    *(float4*)&sm->Q[0][kq][jloc][0] =
                        make_float4(p[0][0], p[0][1], p[0][2], p[0][3]);
                __syncthreads();
                if (kq == 3) {
                    float bv = dk_b1[jglob];
                    float w2v = dk_w2[jglob];
                    float4 q0 = *(const float4*)&sm->Q[0][0][jloc][0];
                    float4 q1 = *(const float4*)&sm->Q[0][1][jloc][0];
                    float4 q2 = *(const float4*)&sm->Q[0][2][jloc][0];
                    float v[G];
                    v[0] = fmaxf(p[0][0] + q0.x + q1.x + q2.x + bv, 0.f) * w2v;
                    v[1] = fmaxf(p[0][1] + q0.y + q1.y + q2.y + bv, 0.f) * w2v;
                    v[2] = fmaxf(p[0][2] + q0.z + q1.z + q2.z + bv, 0.f) * w2v;
                    v[3] = fmaxf(p[0][3] + q0.w + q1.w + q2.w + bv, 0.f) * w2v;
#pragma unroll
                    for (int off = 16; off; off >>= 1)
#pragma unroll
                        for (int g = 0; g < G; g++)
                            v[g] += __shfl_xor_sync(0xffffffffu, v[g], off);
                    if (lane == 0)
#pragma unroll
                        for (int g = 0; g < G; g++) sm->sred[warp & 3][g] = v[g];
                }
                __syncthreads();
                if (tid < G) {
                    float s = sm->sred[0][tid] + sm->sred[1][tid]
                            + sm->sred[2][tid] + sm->sred[3][tid];
                    sm->Dl[tid] = s;
                    st_peer_f1(pDr + (uint32_t)tid * 4u, s);
                }
            }
            CLUSTER_SYNC();  // CS1
            if (tid < G) {
                float dec = fmaxf(sm->Dl[tid] + sm->Dr[tid] + dk_b2[0], 0.f);
                float d = dec * sm->sdt[tid];
                sm->se1[tid] = __expf(-0.5f * d);
                sm->se2[tid] = __expf(-d);
            }
            __syncthreads();

            // ---- elementwise decay (replicated in both CTAs) ----
            for (int it = tid; it < G * 256; it += THREADS) {
                int g = it >> 8, jj = it & 255;
                float yv = sm->sy[g * 256 + jj], ytv = sm->syt[g * 256 + jj];
                float df = yv - ytv;
                sm->smean[g * 256 + jj] = ytv + df * (0.5f * (1.f + sm->se1[g]));
                float ye = ytv + df * sm->se2[g];
                sm->sy[g * 256 + jj] = ye;
                sm->syc[g * GIN + jj] = ye;
            }
            __syncthreads();

            // ---- decoder partial (own 64 columns, half-K per kh) ----
            {
                const ulonglong2* Wd = WP + OFF_DEC + kh * 16 * 128;
                pdec = gemv_dec1(Wd, sm->smean + gd * 256 + kh * 128, jdglob);
                if (kh) sm->Pd[jd][gd] = pdec;
            }
        } else {
            for (int it = tid; it < G * 256; it += THREADS) {
                int g = it >> 8, jj = it & 255;
                sm->syc[g * GIN + jj] = 0.f;
            }
            __syncthreads();
        }

        // ---- gate layer1: ug/ugt/rg y-part (256->own 128 cols) ----
        {
            const ulonglong2* Wg[3] = { WP + OFF_UG1  + r256q,
                                        WP + OFF_UGT1 + r256q,
                                        WP + OFF_RG1  + r256q };
            float p[3][G];
            gemv_part<8, 3, 256, 1>(p, Wg, sm->syc + a256q, GIN, jglob);
            if (kq != 3) {
#pragma unroll
                for (int m = 0; m < 3; m++)
                    *(float4*)&sm->Q[m][kq][jloc][0] =
                        make_float4(p[m][0], p[m][1], p[m][2], p[m][3]);
            }
            __syncthreads();   // also publishes Pd
            if (kq == 3) {
                const float* B1[3] = { ug_b1, ugt_b1, rg_b1 };
                float* SH[3] = { sm->shh0, sm->shh1, sm->shh2 };
                const uint32_t PSH[3] = { pShh0, pShh1, pShh2 };
#pragma unroll
                for (int m = 0; m < 3; m++) {
                    float bv = B1[m][jglob];
                    float4 q0 = *(const float4*)&sm->Q[m][0][jloc][0];
                    float4 q1 = *(const float4*)&sm->Q[m][1][jloc][0];
                    float4 q2 = *(const float4*)&sm->Q[m][2][jloc][0];
                    float4 x0 = *(const float4*)&sm->Qx[m][0][jloc][0];
                    float4 x1 = *(const float4*)&sm->Qx[m][1][jloc][0];
                    float4 x2 = *(const float4*)&sm->Qx[m][2][jloc][0];
                    float4 x3 = *(const float4*)&sm->Qx[m][3][jloc][0];
                    float vv[G] = {
                        p[m][0] + q0.x + q1.x + q2.x + x0.x + x1.x + x2.x + x3.x + bv,
                        p[m][1] + q0.y + q1.y + q2.y + x0.y + x1.y + x2.y + x3.y + bv,
                        p[m][2] + q0.z + q1.z + q2.z + x0.z + x1.z + x2.z + x3.z + bv,
                        p[m][3] + q0.w + q1.w + q2.w + x0.w + x1.w + x2.w + x3.w + bv };
#pragma unroll
                    for (int g = 0; g < G; g++) {
                        float a = tanhf(vv[g]);
                        int idx = g * 256 + jglob;
                        SH[m][idx] = a;
                        st_peer_f1(PSH[m] + (uint32_t)idx * 4u, a);
                    }
                }
            } else if (t > 0 && kh == 0) {
                // decoder finalize -> global (own 64 columns)
                float v = pdec + sm->Pd[jd][gd] + dec_b[jdglob];
                out_vol[((size_t)(tb + gd) * NSTEP + (t - 1)) * DEC_OUT + jdglob] = v;
            }
            pf_l1(WP + OFF_UG2  + rOwn + jglob);
            pf_l1(WP + OFF_UGT2 + rOwn + jglob);
            pf_l1(WP + OFF_RG2  + rOwn + jglob);
        }
        __syncthreads();       // publish local shh (own half) for own-part gemv
        CLUSTER_ARRIVE();      // CS2 arrive (peer-stores of shh released)

        // ---- gate layer2 x3: own-half K before wait, peer-half after ----
        {
            float p[3][G];
            {
                const ulonglong2* Wg[3] = { WP + OFF_UG2  + rOwn,
                                            WP + OFF_UGT2 + rOwn,
                                            WP + OFF_RG2  + rOwn };
                const float* av[3] = { sm->shh0 + aOwn, sm->shh1 + aOwn,
                                       sm->shh2 + aOwn };
                gemv_part_ma<4, 3, 256>(p, Wg, av, 256, jglob);
            }
            CLUSTER_WAIT();    // CS2 wait: peer shh halves arrive
            {
                const ulonglong2* Wg[3] = { WP + OFF_UG2  + rPeer,
                                            WP + OFF_UGT2 + rPeer,
                                            WP + OFF_RG2  + rPeer };
                const float* av[3] = { sm->shh0 + aPeer, sm->shh1 + aPeer,
                                       sm->shh2 + aPeer };
                gemv_part_ma_acc<4, 3, 256>(p, Wg, av, 256, jglob);
            }
            if (kq != 3) {
#pragma unroll
                for (int m = 0; m < 3; m++)
                    *(float4*)&sm->Q[m][kq][jloc][0] =
                        make_float4(p[m][0], p[m][1], p[m][2], p[m][3]);
            }
            __syncthreads();
            if (kq == 3) {
                float b0 = ug_b2[jglob], b1 = ugt_b2[jglob], b2 = rg_b2[jglob];
                float4 q0, q1, q2;
                q0 = *(const float4*)&sm->Q[0][0][jloc][0];
                q1 = *(const float4*)&sm->Q[0][1][jloc][0];
                q2 = *(const float4*)&sm->Q[0][2][jloc][0];
                u[0] = sigmoid_fast(p[0][0] + q0.x + q1.x + q2.x + b0);
                u[1] = sigmoid_fast(p[0][1] + q0.y + q1.y + q2.y + b0);
                u[2] = sigmoid_fast(p[0][2] + q0.z + q1.z + q2.z + b0);
                u[3] = sigmoid_fast(p[0][3] + q0.w + q1.w + q2.w + b0);
                q0 = *(const float4*)&sm->Q[1][0][jloc][0];
                q1 = *(const float4*)&sm->Q[1][1][jloc][0];
                q2 = *(const float4*)&sm->Q[1][2][jloc][0];
                ut[0] = sigmoid_fast(p[1][0] + q0.x + q1.x + q2.x + b1);
                ut[1] = sigmoid_fast(p[1][1] + q0.y + q1.y + q2.y + b1);
                ut[2] = sigmoid_fast(p[1][2] + q0.z + q1.z + q2.z + b1);
                ut[3] = sigmoid_fast(p[1][3] + q0.w + q1.w + q2.w + b1);
                q0 = *(const float4*)&sm->Q[2][0][jloc][0];
                q1 = *(const float4*)&sm->Q[2][1][jloc][0];
                q2 = *(const float4*)&sm->Q[2][2][jloc][0];
                float rr[G] = { sigmoid_fast(p[2][0] + q0.x + q1.x + q2.x + b2),
                                sigmoid_fast(p[2][1] + q0.y + q1.y + q2.y + b2),
                                sigmoid_fast(p[2][2] + q0.z + q1.z + q2.z + b2),
                                sigmoid_fast(p[2][3] + q0.w + q1.w + q2.w + b2) };
#pragma unroll
                for (int g = 0; g < G; g++) {
                    int idx = g * GIN + jglob;
                    float v = sm->syc[idx] * rr[g];
                    sm->syc[idx] = v;
                    st_peer_f1(pSyc + (uint32_t)idx * 4u, v);
                }
            }
            pf_l1(WP + OFF_NS1 + rOwn + jglob);
        }
        __syncthreads();       // publish local syc head (own half)
        CLUSTER_ARRIVE();      // CS3 arrive

        // ---- new_state layer1: own-half y before wait, peer after; +xh ----
        {
            float p[1][G];
            {
                const ulonglong2* Wg[1] = { WP + OFF_NS1 + rOwn };
                gemv_part<4, 1, 256, 1>(p, Wg, sm->syc + aOwn, GIN, jglob);
            }
            CLUSTER_WAIT();    // CS3 wait: peer syc head arrives
            {
                const ulonglong2* Wg[1] = { WP + OFF_NS1 + rPeer };
                gemv_part_acc<4, 1, 256, 1>(p, Wg, sm->syc + aPeer, GIN, jglob);
            }
            if (kq != 3)
                *(float4*)&sm->Q[0][kq][jloc][0] =
                    make_float4(p[0][0], p[0][1], p[0][2], p[0][3]);
            __syncthreads();
            if (kq == 3) {
                float bv = ns_b1[jglob];
                float4 q0 = *(const float4*)&sm->Q[0][0][jloc][0];
                float4 q1 = *(const float4*)&sm->Q[0][1][jloc][0];
                float4 q2 = *(const float4*)&sm->Q[0][2][jloc][0];
                float4 x0 = *(const float4*)&sm->Qx[3][0][jloc][0];
                float4 x1 = *(const float4*)&sm->Qx[3][1][jloc][0];
                float4 x2 = *(const float4*)&sm->Qx[3][2][jloc][0];
                float4 x3 = *(const float4*)&sm->Qx[3][3][jloc][0];
                float vv[G] = {
                    p[0][0] + q0.x + q1.x + q2.x + x0.x + x1.x + x2.x + x3.x + bv,
                    p[0][1] + q0.y + q1.y + q2.y + x0.y + x1.y + x2.y + x3.y + bv,
                    p[0][2] + q0.z + q1.z + q2.z + x0.z + x1.z + x2.z + x3.z + bv,
                    p[0][3] + q0.w + q1.w + q2.w + x0.w + x1.w + x2.w + x3.w + bv };
#pragma unroll
                for (int g = 0; g < G; g++) {
                    float a = tanhf(vv[g]);
                    int idx = g * 256 + jglob;
                    sm->shh0[idx] = a;
                    st_peer_f1(pShh0 + (uint32_t)idx * 4u, a);
                }
            }
            pf_l1(WP + OFF_NS2 + rOwn + jglob);
        }
        __syncthreads();       // publish local shh0 (own half)
        CLUSTER_ARRIVE();      // CS4 arrive

        // ---- new_state layer2: own-half before wait, peer after; update ----
        {
            float p[1][G];
            {
                const ulonglong2* Wg[1] = { WP + OFF_NS2 + rOwn };
                gemv_part<4, 1, 256, 1>(p, Wg, sm->shh0 + aOwn, 256, jglob);
            }
            CLUSTER_WAIT();    // CS4 wait
            {
                const ulonglong2* Wg[1] = { WP + OFF_NS2 + rPeer };
                gemv_part_acc<4, 1, 256, 1>(p, Wg, sm->shh0 + aPeer, 256, jglob);
            }
            if (kq != 3)
                *(float4*)&sm->Q[0][kq][jloc][0] =
                    make_float4(p[0][0], p[0][1], p[0][2], p[0][3]);
            __syncthreads();
            if (kq == 3) {
                float bv = ns_b2[jglob];
                float4 q0 = *(const float4*)&sm->Q[0][0][jloc][0];
                float4 q1 = *(const float4*)&sm->Q[0][1][jloc][0];
                float4 q2 = *(const float4*)&sm->Q[0][2][jloc][0];
                float nsv[G] = { p[0][0] + q0.x + q1.x + q2.x + bv,
                                 p[0][1] + q0.y + q1.y + q2.y + bv,
                                 p[0][2] + q0.z + q1.z + q2.z + bv,
                                 p[0][3] + q0.w + q1.w + q2.w + bv };
#pragma unroll
                for (int g = 0; g < G; g++) {
                    float m    = sm->smask[g];
                    int idx    = g * 256 + jglob;
                    float yend = sm->sy[idx], ytv = sm->syt[idx];
                    float ny   = (1.f - u[g])  * nsv[g] + u[g]  * yend;
                    float nyt  = (1.f - ut[g]) * nsv[g] + ut[g] * ytv;
                    float oy   = m * ny  + (1.f - m) * yend;
                    float oyt  = m * nyt + (1.f - m) * ytv;
                    sm->sy[idx]  = oy;
                    sm->syt[idx] = oyt;
                    st_peer_f1(pSy  + (uint32_t)idx * 4u, oy);
                    st_peer_f1(pSyt + (uint32_t)idx * 4u, oyt);
                }
            }
        }
        CLUSTER_ARRIVE();      // S0 arrive for next step (state released)
    }

    CLUSTER_WAIT();            // final pairing
    if (rank == 0 && tid < 256) {
#pragma unroll
        for (int g = 0; g < G; g++)
            out_prev[(size_t)(tb + g) * LATENT + tid] = sm->sy[g * 256 + tid];
    }
}

extern "C" void kernel_launch(void* const* d_in, const int* in_sizes, int n_in,
                              void* d_out, int out_size) {
    const float* data   = (const float*)d_in[0];
    const float* ts     = (const float*)d_in[1];
    const float* ug_w1  = (const float*)d_in[2];
    const float* ug_b1  = (const float*)d_in[3];
    const float* ug_w2  = (const float*)d_in[4];
    const float* ug_b2  = (const float*)d_in[5];
    const float* ugt_w1 = (const float*)d_in[6];
    const float* ugt_b1 = (const float*)d_in[7];
    const float* ugt_w2 = (const float*)d_in[8];
    const float* ugt_b2 = (const float*)d_in[9];
    const float* rg_w1  = (const float*)d_in[10];
    const float* rg_b1  = (const float*)d_in[11];
    const float* rg_w2  = (const float*)d_in[12];
    const float* rg_b2  = (const float*)d_in[13];
    // d_in[14..17] = rgt_* : unused by the reference
    const float* ns_w1  = (const float*)d_in[18];
    const float* ns_b1  = (const float*)d_in[19];
    const float* ns_w2  = (const float*)d_in[20];
    const float* ns_b2  = (const float*)d_in[21];
    const float* dk_w1  = (const float*)d_in[22];
    const float* dk_b1  = (const float*)d_in[23];
    const float* dk_w2  = (const float*)d_in[24];
    const float* dk_b2  = (const float*)d_in[25];
    const float* dec_w  = (const float*)d_in[26];
    const float* dec_b  = (const float*)d_in[27];

    cudaFuncSetAttribute(rnn_decay_kernel,
                         cudaFuncAttributeMaxDynamicSharedMemorySize, SMEM_BYTES);

    pack_kernel<<<(WP_TOTAL + 255) / 256, 256>>>(
        ug_w1, ugt_w1, rg_w1, ns_w1, ug_w2, ugt_w2, rg_w2, ns_w2, dk_w1, dec_w);

    rnn_decay_kernel<<<NBLK, THREADS, SMEM_BYTES>>>(
        data, ts,
        ug_b1, ug_b2, ugt_b1, ugt_b2, rg_b1, rg_b2,
        ns_b1, ns_b2, dk_b1, dk_w2, dk_b2, dec_b,
        (float*)d_out);
}